// round 2
// baseline (speedup 1.0000x reference)
#include <cuda_runtime.h>
#include <math.h>
#include <stdint.h>

#define QLEN   512
#define MLEN   512
#define KLEN   1024
#define RLEN   1536
#define BATCH  4
#define DMODEL 1024
#define NHEAD  16
#define DHEAD  64
#define BN_TOT (BATCH*NHEAD)
#define SCALE_F 0.125f
#define LN_EPS 1e-3f

// ---------------- scratch (device globals; no allocation allowed) ----------------
__device__ float g_cat[(size_t)KLEN*BATCH*DMODEL];     // 16 MB
__device__ float g_q  [(size_t)QLEN*BATCH*DMODEL];     // 8 MB
__device__ float g_k  [(size_t)KLEN*BATCH*DMODEL];     // 16 MB
__device__ float g_v  [(size_t)KLEN*BATCH*DMODEL];     // 16 MB
__device__ float g_kr [(size_t)RLEN*BATCH*DMODEL];     // 24 MB
__device__ float g_e  [QLEN*BATCH*NHEAD*2];
__device__ float g_rwk [BN_TOT*KLEN];
__device__ float g_rrkr[BN_TOT*RLEN];
__device__ float g_scores[(size_t)BN_TOT*QLEN*KLEN];   // 128 MB
__device__ float g_vec[(size_t)QLEN*BATCH*DMODEL];     // 8 MB
__device__ float g_att[(size_t)QLEN*BATCH*DMODEL];     // 8 MB

// ---------------- generic tiled SGEMM: C = A(MxK,rm) * B(KxN,rm) ----------------
__global__ __launch_bounds__(256) void sgemm_nn(const float* __restrict__ A,
                                                const float* __restrict__ B,
                                                float* __restrict__ C,
                                                int M, int N, int K)
{
    __shared__ float As[16][128];
    __shared__ float Bs[16][132];
    const int tid = threadIdx.x;
    const int tx = tid & 15, ty = tid >> 4;
    const int bm = blockIdx.y << 7;
    const int bnn = blockIdx.x << 7;
    float acc[8][8] = {};
    for (int k0 = 0; k0 < K; k0 += 16) {
        #pragma unroll
        for (int l = 0; l < 2; l++) {
            int s = tid + l*256;
            int row = s >> 2, kq = (s & 3) * 4;
            float4 a = *(const float4*)&A[(size_t)(bm+row)*K + k0 + kq];
            As[kq+0][row] = a.x; As[kq+1][row] = a.y;
            As[kq+2][row] = a.z; As[kq+3][row] = a.w;
        }
        #pragma unroll
        for (int l = 0; l < 2; l++) {
            int s = tid + l*256;
            int krow = s >> 5, nq = (s & 31) * 4;
            *(float4*)&Bs[krow][nq] = *(const float4*)&B[(size_t)(k0+krow)*N + bnn + nq];
        }
        __syncthreads();
        #pragma unroll
        for (int kk = 0; kk < 16; kk++) {
            float ra[8], rb[8];
            *(float4*)&ra[0] = *(float4*)&As[kk][ty*8];
            *(float4*)&ra[4] = *(float4*)&As[kk][ty*8+4];
            *(float4*)&rb[0] = *(float4*)&Bs[kk][tx*8];
            *(float4*)&rb[4] = *(float4*)&Bs[kk][tx*8+4];
            #pragma unroll
            for (int u = 0; u < 8; u++)
                #pragma unroll
                for (int v = 0; v < 8; v++)
                    acc[u][v] += ra[u]*rb[v];
        }
        __syncthreads();
    }
    #pragma unroll
    for (int u = 0; u < 8; u++) {
        int row = bm + ty*8 + u;
        #pragma unroll
        for (int v = 0; v < 8; v += 4)
            *(float4*)&C[(size_t)row*N + bnn + tx*8 + v] = *(float4*)&acc[u][v];
    }
}

// C = A(MxK,rm) * B(NxK,rm)^T
__global__ __launch_bounds__(256) void sgemm_nt(const float* __restrict__ A,
                                                const float* __restrict__ B,
                                                float* __restrict__ C,
                                                int M, int N, int K)
{
    __shared__ float As[16][128];
    __shared__ float Bs[16][132];
    const int tid = threadIdx.x;
    const int tx = tid & 15, ty = tid >> 4;
    const int bm = blockIdx.y << 7;
    const int bnn = blockIdx.x << 7;
    float acc[8][8] = {};
    for (int k0 = 0; k0 < K; k0 += 16) {
        #pragma unroll
        for (int l = 0; l < 2; l++) {
            int s = tid + l*256;
            int row = s >> 2, kq = (s & 3) * 4;
            float4 a = *(const float4*)&A[(size_t)(bm+row)*K + k0 + kq];
            As[kq+0][row] = a.x; As[kq+1][row] = a.y;
            As[kq+2][row] = a.z; As[kq+3][row] = a.w;
        }
        #pragma unroll
        for (int l = 0; l < 2; l++) {
            int s = tid + l*256;
            int nrow = s >> 2, kq = (s & 3) * 4;
            float4 bv = *(const float4*)&B[(size_t)(bnn+nrow)*K + k0 + kq];
            Bs[kq+0][nrow] = bv.x; Bs[kq+1][nrow] = bv.y;
            Bs[kq+2][nrow] = bv.z; Bs[kq+3][nrow] = bv.w;
        }
        __syncthreads();
        #pragma unroll
        for (int kk = 0; kk < 16; kk++) {
            float ra[8], rb[8];
            *(float4*)&ra[0] = *(float4*)&As[kk][ty*8];
            *(float4*)&ra[4] = *(float4*)&As[kk][ty*8+4];
            #pragma unroll
            for (int v = 0; v < 8; v++) rb[v] = Bs[kk][tx*8+v];
            #pragma unroll
            for (int u = 0; u < 8; u++)
                #pragma unroll
                for (int v = 0; v < 8; v++)
                    acc[u][v] += ra[u]*rb[v];
        }
        __syncthreads();
    }
    #pragma unroll
    for (int u = 0; u < 8; u++) {
        int row = bm + ty*8 + u;
        #pragma unroll
        for (int v = 0; v < 8; v += 4)
            *(float4*)&C[(size_t)row*N + bnn + tx*8 + v] = *(float4*)&acc[u][v];
    }
}

// ---------------- bias dot tables ----------------
// g_rwk[(b*16+n)*KLEN + j] = sum_d rw[n,d] * k[j,b,n,d]
__global__ void rwk_kernel(const float* __restrict__ rw)
{
    int idx = blockIdx.x*blockDim.x + threadIdx.x;      // 65536
    int j = idx & (KLEN-1);
    int bn = idx >> 10;
    int b = bn >> 4, n = bn & 15;
    const float* krow = &g_k[((size_t)j*BATCH + b)*DMODEL + n*DHEAD];
    const float* w = &rw[n*DHEAD];
    float s = 0.f;
    #pragma unroll 16
    for (int d = 0; d < DHEAD; d++) s += w[d]*krow[d];
    g_rwk[idx] = s;
}

// g_rrkr[(b*16+n)*RLEN + jr] = sum_d rr[n,d] * kr[jr,b,n,d]
__global__ void rrkr_kernel(const float* __restrict__ rr)
{
    int idx = blockIdx.x*blockDim.x + threadIdx.x;      // 98304
    int jr = idx % RLEN;
    int bn = idx / RLEN;
    int b = bn >> 4, n = bn & 15;
    const float* krow = &g_kr[((size_t)jr*BATCH + b)*DMODEL + n*DHEAD];
    const float* w = &rr[n*DHEAD];
    float s = 0.f;
    #pragma unroll 16
    for (int d = 0; d < DHEAD; d++) s += w[d]*krow[d];
    g_rrkr[idx] = s;
}

// g_e[((i*4+b)*16+n)*2+s] = sum_d (q[i,b,n,d]+rs[n,d]) * seg_embed[s,n,d]
__global__ void e_kernel(const float* __restrict__ rs, const float* __restrict__ seg)
{
    int idx = blockIdx.x*blockDim.x + threadIdx.x;      // 32768
    int n = idx & 15;
    int ib = idx >> 4;
    int b = ib & 3, i = ib >> 2;
    const float* q = &g_q[((size_t)i*BATCH + b)*DMODEL + n*DHEAD];
    const float* w = &rs[n*DHEAD];
    const float* s0p = &seg[(0*NHEAD + n)*DHEAD];
    const float* s1p = &seg[(1*NHEAD + n)*DHEAD];
    float s0 = 0.f, s1 = 0.f;
    #pragma unroll 16
    for (int d = 0; d < DHEAD; d++) {
        float qr = q[d] + w[d];
        s0 += qr*s0p[d];
        s1 += qr*s1p[d];
    }
    g_e[idx*2+0] = s0;
    g_e[idx*2+1] = s1;
}

// ---------------- scores: (ac + bd(shifted) + ef)*SCALE - 1e30*mask ----------------
// grid: (j-tiles=16, i-tiles=8, bn=64). Dynamic smem 256*68*4 = 69632 B.
__global__ __launch_bounds__(256) void score_kernel(const float* __restrict__ seg_mat,
                                                    const float* __restrict__ attn_mask)
{
    extern __shared__ float smf[];
    const int ST = 68;
    float* Qs  = smf;              // 64 x ST
    float* Ks  = smf + 64*ST;      // 64 x ST
    float* Krs = smf + 128*ST;     // 128 x ST
    const int bn = blockIdx.z, b = bn >> 4, n = bn & 15;
    const int i0 = blockIdx.y << 6, j0 = blockIdx.x << 6;
    const int krbase = j0 + 512 - i0 - 63;
    const int tid = threadIdx.x, tx = tid & 15, ty = tid >> 4;
    const int cbase = n*DHEAD;

    for (int t = tid; t < 64*16; t += 256) {
        int rrow = t >> 4, c4 = (t & 15) * 4;
        *(float4*)&Qs[rrow*ST + c4] =
            *(const float4*)&g_q[((size_t)(i0+rrow)*BATCH + b)*DMODEL + cbase + c4];
        *(float4*)&Ks[rrow*ST + c4] =
            *(const float4*)&g_k[((size_t)(j0+rrow)*BATCH + b)*DMODEL + cbase + c4];
    }
    for (int t = tid; t < 128*16; t += 256) {
        int rrow = t >> 4, c4 = (t & 15) * 4;
        int jr = krbase + rrow; if (jr > RLEN-1) jr = RLEN-1;
        *(float4*)&Krs[rrow*ST + c4] =
            *(const float4*)&g_kr[((size_t)jr*BATCH + b)*DMODEL + cbase + c4];
    }
    __syncthreads();

    float acc[4][4] = {};
    const int qrow = ty*4, kcol = tx*4;
    const int dbase = kcol - qrow + 60;   // + (jj-ii+3) gives local Kr row

    #pragma unroll 4
    for (int d = 0; d < DHEAD; d++) {
        float qv[4], kv[4], krv[7];
        #pragma unroll
        for (int u = 0; u < 4; u++) qv[u] = Qs[(qrow+u)*ST + d];
        #pragma unroll
        for (int u = 0; u < 4; u++) kv[u] = Ks[(kcol+u)*ST + d];
        #pragma unroll
        for (int t = 0; t < 7; t++) krv[t] = Krs[(dbase+t)*ST + d];
        #pragma unroll
        for (int ii = 0; ii < 4; ii++)
            #pragma unroll
            for (int jj = 0; jj < 4; jj++)
                acc[ii][jj] += qv[ii]*(kv[jj] + krv[jj-ii+3]);
    }

    const float* rwk  = &g_rwk[bn*KLEN];
    const float* rrkr = &g_rrkr[bn*RLEN];
    #pragma unroll
    for (int ii = 0; ii < 4; ii++) {
        int i = i0 + qrow + ii;
        float e0 = g_e[(((size_t)i*BATCH + b)*NHEAD + n)*2 + 0];
        float e1 = g_e[(((size_t)i*BATCH + b)*NHEAD + n)*2 + 1];
        #pragma unroll
        for (int jj = 0; jj < 4; jj++) {
            int j = j0 + kcol + jj;
            int jr = j + 512 - i;
            size_t mi = ((size_t)i*KLEN + j)*BATCH + b;
            float sm0 = seg_mat[mi*2+0], sm1 = seg_mat[mi*2+1];
            float sc = (acc[ii][jj] + rwk[j] + rrkr[jr] + sm0*e0 + sm1*e1) * SCALE_F
                       - 1e30f * attn_mask[mi];
            g_scores[((size_t)bn*QLEN + i)*KLEN + j] = sc;
        }
    }
}

// ---------------- softmax along j (1024), in place ----------------
__global__ __launch_bounds__(256) void softmax_kernel()
{
    __shared__ float red[8];
    __shared__ float bcast;
    float* p = &g_scores[(size_t)blockIdx.x * KLEN];
    const int tid = threadIdx.x;
    float4 v = ((float4*)p)[tid];

    float m = fmaxf(fmaxf(v.x, v.y), fmaxf(v.z, v.w));
    #pragma unroll
    for (int o = 16; o; o >>= 1) m = fmaxf(m, __shfl_xor_sync(0xffffffffu, m, o));
    if ((tid & 31) == 0) red[tid >> 5] = m;
    __syncthreads();
    if (tid < 32) {
        float t = (tid < 8) ? red[tid] : -INFINITY;
        #pragma unroll
        for (int o = 4; o; o >>= 1) t = fmaxf(t, __shfl_xor_sync(0xffffffffu, t, o));
        if (tid == 0) bcast = t;
    }
    __syncthreads();
    m = bcast;
    __syncthreads();

    v.x = __expf(v.x - m); v.y = __expf(v.y - m);
    v.z = __expf(v.z - m); v.w = __expf(v.w - m);
    float s = v.x + v.y + v.z + v.w;
    #pragma unroll
    for (int o = 16; o; o >>= 1) s += __shfl_xor_sync(0xffffffffu, s, o);
    if ((tid & 31) == 0) red[tid >> 5] = s;
    __syncthreads();
    if (tid < 32) {
        float t = (tid < 8) ? red[tid] : 0.f;
        #pragma unroll
        for (int o = 4; o; o >>= 1) t += __shfl_xor_sync(0xffffffffu, t, o);
        if (tid == 0) bcast = 1.0f / t;
    }
    __syncthreads();
    float inv = bcast;
    v.x *= inv; v.y *= inv; v.z *= inv; v.w *= inv;
    ((float4*)p)[tid] = v;
}

// ---------------- attn_vec = prob @ v per (b,n) ----------------
// grid: (i-tiles=8, bn=64)
__global__ __launch_bounds__(256) void pv_kernel()
{
    __shared__ float Ps[64][68];
    __shared__ float Vs[64][68];
    const int bn = blockIdx.y, b = bn >> 4, n = bn & 15;
    const int i0 = blockIdx.x << 6;
    const int tid = threadIdx.x, tx = tid & 15, ty = tid >> 4;
    float acc[4][4] = {};
    for (int j0 = 0; j0 < KLEN; j0 += 64) {
        for (int t = tid; t < 64*16; t += 256) {
            int rrow = t >> 4, c4 = (t & 15) * 4;
            *(float4*)&Ps[rrow][c4] =
                *(const float4*)&g_scores[((size_t)bn*QLEN + i0 + rrow)*KLEN + j0 + c4];
            *(float4*)&Vs[rrow][c4] =
                *(const float4*)&g_v[((size_t)(j0+rrow)*BATCH + b)*DMODEL + n*DHEAD + c4];
        }
        __syncthreads();
        #pragma unroll 8
        for (int jj = 0; jj < 64; jj++) {
            float pv[4], vv[4];
            #pragma unroll
            for (int u = 0; u < 4; u++) pv[u] = Ps[ty*4+u][jj];
            #pragma unroll
            for (int u = 0; u < 4; u++) vv[u] = Vs[jj][tx*4+u];
            #pragma unroll
            for (int ii = 0; ii < 4; ii++)
                #pragma unroll
                for (int dd = 0; dd < 4; dd++)
                    acc[ii][dd] += pv[ii]*vv[dd];
        }
        __syncthreads();
    }
    #pragma unroll
    for (int ii = 0; ii < 4; ii++)
        *(float4*)&g_vec[((size_t)(i0+ty*4+ii)*BATCH + b)*DMODEL + n*DHEAD + tx*4] =
            *(float4*)&acc[ii][0];
}

// ---------------- out = layer_norm(attn_out + h) ----------------
__global__ __launch_bounds__(256) void addln_kernel(const float* __restrict__ h,
                                                    const float* __restrict__ gamma,
                                                    const float* __restrict__ beta,
                                                    float* __restrict__ out)
{
    __shared__ float red[8];
    __shared__ float bc;
    const int row = blockIdx.x;
    const int tid = threadIdx.x;
    float4 x  = ((const float4*)&g_att[(size_t)row*DMODEL])[tid];
    float4 hh = ((const float4*)&h[(size_t)row*DMODEL])[tid];
    x.x += hh.x; x.y += hh.y; x.z += hh.z; x.w += hh.w;

    float s = x.x + x.y + x.z + x.w;
    #pragma unroll
    for (int o = 16; o; o >>= 1) s += __shfl_xor_sync(0xffffffffu, s, o);
    if ((tid & 31) == 0) red[tid >> 5] = s;
    __syncthreads();
    if (tid < 32) {
        float t = (tid < 8) ? red[tid] : 0.f;
        #pragma unroll
        for (int o = 4; o; o >>= 1) t += __shfl_xor_sync(0xffffffffu, t, o);
        if (tid == 0) bc = t * (1.0f/DMODEL);
    }
    __syncthreads();
    float mu = bc;
    __syncthreads();

    float dx0 = x.x - mu, dx1 = x.y - mu, dx2 = x.z - mu, dx3 = x.w - mu;
    float sq = dx0*dx0 + dx1*dx1 + dx2*dx2 + dx3*dx3;
    #pragma unroll
    for (int o = 16; o; o >>= 1) sq += __shfl_xor_sync(0xffffffffu, sq, o);
    if ((tid & 31) == 0) red[tid >> 5] = sq;
    __syncthreads();
    if (tid < 32) {
        float t = (tid < 8) ? red[tid] : 0.f;
        #pragma unroll
        for (int o = 4; o; o >>= 1) t += __shfl_xor_sync(0xffffffffu, t, o);
        if (tid == 0) bc = rsqrtf(t * (1.0f/DMODEL) + LN_EPS);
    }
    __syncthreads();
    float inv = bc;

    float4 g = ((const float4*)gamma)[tid];
    float4 bt = ((const float4*)beta)[tid];
    float4 o4;
    o4.x = dx0*inv*g.x + bt.x;
    o4.y = dx1*inv*g.y + bt.y;
    o4.z = dx2*inv*g.z + bt.z;
    o4.w = dx3*inv*g.w + bt.w;
    ((float4*)&out[(size_t)row*DMODEL])[tid] = o4;
}

// ---------------- launch ----------------
extern "C" void kernel_launch(void* const* d_in, const int* in_sizes, int n_in,
                              void* d_out, int out_size)
{
    (void)in_sizes; (void)n_in; (void)out_size;
    const float* rw        = (const float*)d_in[0];
    const float* rs        = (const float*)d_in[1];
    const float* rr        = (const float*)d_in[2];
    const float* seg_embed = (const float*)d_in[3];
    const float* h         = (const float*)d_in[4];
    const float* r         = (const float*)d_in[5];
    const float* mems      = (const float*)d_in[6];
    const float* seg_mat   = (const float*)d_in[7];
    const float* attn_mask = (const float*)d_in[8];
    const float* wq        = (const float*)d_in[9];
    const float* wk        = (const float*)d_in[10];
    const float* wv        = (const float*)d_in[11];
    const float* wr        = (const float*)d_in[12];
    const float* wo        = (const float*)d_in[13];
    const float* gamma     = (const float*)d_in[14];
    const float* beta      = (const float*)d_in[15];

    void *p_cat, *p_q, *p_k, *p_v, *p_kr, *p_vec, *p_att;
    cudaGetSymbolAddress(&p_cat, g_cat);
    cudaGetSymbolAddress(&p_q,   g_q);
    cudaGetSymbolAddress(&p_k,   g_k);
    cudaGetSymbolAddress(&p_v,   g_v);
    cudaGetSymbolAddress(&p_kr,  g_kr);
    cudaGetSymbolAddress(&p_vec, g_vec);
    cudaGetSymbolAddress(&p_att, g_att);

    const size_t half = (size_t)MLEN*BATCH*DMODEL;
    cudaMemcpyAsync(p_cat, mems, half*sizeof(float), cudaMemcpyDeviceToDevice, 0);
    cudaMemcpyAsync((float*)p_cat + half, h, half*sizeof(float), cudaMemcpyDeviceToDevice, 0);

    // projections
    sgemm_nn<<<dim3(8,16), 256>>>(h,            wq, (float*)p_q,  QLEN*BATCH, DMODEL, DMODEL);
    sgemm_nn<<<dim3(8,32), 256>>>((float*)p_cat, wk, (float*)p_k,  KLEN*BATCH, DMODEL, DMODEL);
    sgemm_nn<<<dim3(8,32), 256>>>((float*)p_cat, wv, (float*)p_v,  KLEN*BATCH, DMODEL, DMODEL);
    sgemm_nn<<<dim3(8,48), 256>>>(r,            wr, (float*)p_kr, RLEN*BATCH, DMODEL, DMODEL);

    // bias dot tables
    rwk_kernel<<<BN_TOT*KLEN/256, 256>>>(rw);
    rrkr_kernel<<<BN_TOT*RLEN/256, 256>>>(rr);
    e_kernel<<<QLEN*BATCH*NHEAD/256, 256>>>(rs, seg_embed);

    // scores
    cudaFuncSetAttribute(score_kernel, cudaFuncAttributeMaxDynamicSharedMemorySize, 256*68*4);
    score_kernel<<<dim3(16,8,64), 256, 256*68*4>>>(seg_mat, attn_mask);

    // softmax
    softmax_kernel<<<BN_TOT*QLEN, 256>>>();

    // attn_vec
    pv_kernel<<<dim3(8,64), 256>>>();

    // attn_out = vec @ wo^T
    sgemm_nt<<<dim3(8,16), 256>>>((float*)p_vec, wo, (float*)p_att, QLEN*BATCH, DMODEL, DMODEL);

    // layernorm(attn_out + h)
    addln_kernel<<<QLEN*BATCH, 256>>>(h, gamma, beta, (float*)d_out);
}

// round 3
// speedup vs baseline: 1.4207x; 1.4207x over previous
#include <cuda_runtime.h>
#include <math.h>
#include <stdint.h>

#define QLEN   512
#define MLEN   512
#define KLEN   1024
#define RLEN   1536
#define BATCH  4
#define DMODEL 1024
#define NHEAD  16
#define DHEAD  64
#define BN_TOT (BATCH*NHEAD)
#define SCALE_F 0.125f
#define LN_EPS 1e-3f

// ---------------- scratch (device globals; no allocation allowed) ----------------
__device__ float g_q  [(size_t)QLEN*BATCH*DMODEL];     // 8 MB
__device__ float g_k  [(size_t)KLEN*BATCH*DMODEL];     // 16 MB
__device__ float g_v  [(size_t)KLEN*BATCH*DMODEL];     // 16 MB
__device__ float g_kr [(size_t)RLEN*BATCH*DMODEL];     // 24 MB
__device__ float g_e  [QLEN*BATCH*NHEAD*2];
__device__ float g_rwk [BN_TOT*KLEN];
__device__ float g_rrkr[BN_TOT*RLEN];
__device__ float g_scores[(size_t)BN_TOT*QLEN*KLEN];   // 128 MB
__device__ float g_vec[(size_t)QLEN*BATCH*DMODEL];     // 8 MB
__device__ float g_att[(size_t)QLEN*BATCH*DMODEL];     // 8 MB

// tf32-converted operands
__device__ unsigned g_ht  [(size_t)QLEN*BATCH*DMODEL];   // h
__device__ unsigned g_catt[(size_t)KLEN*BATCH*DMODEL];   // [mems; h]
__device__ unsigned g_rt  [(size_t)RLEN*BATCH*DMODEL];   // r
__device__ unsigned g_wqt [DMODEL*DMODEL];
__device__ unsigned g_wkt [DMODEL*DMODEL];
__device__ unsigned g_wvt [DMODEL*DMODEL];
__device__ unsigned g_wrt [DMODEL*DMODEL];
__device__ unsigned g_wot [DMODEL*DMODEL];
__device__ unsigned g_vect[(size_t)QLEN*BATCH*DMODEL];

// ---------------- fp32 -> tf32 (round-to-nearest) convert ----------------
__device__ __forceinline__ unsigned f2tf(float f) {
    unsigned u;
    asm("cvt.rna.tf32.f32 %0, %1;" : "=r"(u) : "f"(f));
    return u;
}

__global__ __launch_bounds__(256) void cvt_tf32(const float* __restrict__ in,
                                                unsigned* __restrict__ out)
{
    int i = blockIdx.x*256 + threadIdx.x;
    float4 v = ((const float4*)in)[i];
    uint4 o;
    o.x = f2tf(v.x); o.y = f2tf(v.y); o.z = f2tf(v.z); o.w = f2tf(v.w);
    ((uint4*)out)[i] = o;
}

// ---------------- tf32 tensor-core GEMM ----------------
// NT==0: C[M,1024] = A[M,1024] * B[1024,1024]        (B row-major [K,N])
// NT==1: C[M,1024] = A[M,1024] * B[1024,1024]^T      (B row-major [N,K])
#define AST 36     // A smem row stride (words)
#define BSTN 132   // nn B smem row stride
#define BSTT 36    // nt B smem row stride

__device__ __forceinline__ void cp16(unsigned* dst, const unsigned* src) {
    unsigned d = (unsigned)__cvta_generic_to_shared(dst);
    asm volatile("cp.async.cg.shared.global [%0], [%1], 16;" :: "r"(d), "l"(src));
}
__device__ __forceinline__ void mma_tf32(float* c, const unsigned* a, const unsigned* b) {
    asm volatile("mma.sync.aligned.m16n8k8.row.col.f32.tf32.tf32.f32 "
                 "{%0,%1,%2,%3}, {%4,%5,%6,%7}, {%8,%9}, {%0,%1,%2,%3};"
                 : "+f"(c[0]), "+f"(c[1]), "+f"(c[2]), "+f"(c[3])
                 : "r"(a[0]), "r"(a[1]), "r"(a[2]), "r"(a[3]), "r"(b[0]), "r"(b[1]));
}

template<int NT>
__global__ __launch_bounds__(256, 2) void gemm_tf32(const unsigned* __restrict__ A,
                                                    const unsigned* __restrict__ B,
                                                    float* __restrict__ C, int M)
{
    constexpr int N = 1024, K = 1024;
    constexpr int ASZ = 128*AST;
    constexpr int BSZ = NT ? 128*BSTT : 32*BSTN;
    constexpr int NIT = K/32;
    extern __shared__ unsigned sm[];
    unsigned* sA[2] = { sm,        sm + ASZ + BSZ };
    unsigned* sB[2] = { sm + ASZ,  sm + 2*ASZ + BSZ };

    const int tid = threadIdx.x;
    const int m0 = blockIdx.y << 7;
    const int n0 = blockIdx.x << 7;
    const int lane = tid & 31, wid = tid >> 5;
    const int wr = wid >> 2, wc = wid & 3;

    float acc[4][4][4] = {};

    // ---- issue lambda-ish macro via inline loop ----
    auto issue = [&](int it, int st) {
        int k0 = it * 32;
        #pragma unroll
        for (int q = 0; q < 4; q++) {
            int idx = tid + 256*q;
            int row = idx >> 3, kc = (idx & 7) * 4;
            cp16(&sA[st][row*AST + kc], &A[(size_t)(m0+row)*K + k0 + kc]);
        }
        if (NT) {
            #pragma unroll
            for (int q = 0; q < 4; q++) {
                int idx = tid + 256*q;
                int row = idx >> 3, kc = (idx & 7) * 4;
                cp16(&sB[st][row*BSTT + kc], &B[(size_t)(n0+row)*K + k0 + kc]);
            }
        } else {
            #pragma unroll
            for (int q = 0; q < 4; q++) {
                int idx = tid + 256*q;
                int row = idx >> 5, nc = (idx & 31) * 4;
                cp16(&sB[st][row*BSTN + nc], &B[(size_t)(k0+row)*N + n0 + nc]);
            }
        }
        asm volatile("cp.async.commit_group;");
    };

    issue(0, 0);
    for (int it = 0; it < NIT; it++) {
        int st = it & 1;
        if (it + 1 < NIT) issue(it+1, st^1);
        if (it + 1 < NIT) asm volatile("cp.async.wait_group 1;");
        else              asm volatile("cp.async.wait_group 0;");
        __syncthreads();

        const unsigned* Ab = sA[st] + (wr*64 + (lane>>2))*AST + (lane&3);
        #pragma unroll
        for (int ks = 0; ks < 4; ks++) {
            unsigned a[4][4];
            #pragma unroll
            for (int mt = 0; mt < 4; mt++) {
                const unsigned* p = Ab + mt*16*AST + ks*8;
                a[mt][0] = p[0];
                a[mt][1] = p[8*AST];
                a[mt][2] = p[4];
                a[mt][3] = p[8*AST + 4];
            }
            unsigned b[4][2];
            #pragma unroll
            for (int nt = 0; nt < 4; nt++) {
                if (NT) {
                    const unsigned* p = sB[st] + (wc*32 + nt*8 + (lane>>2))*BSTT + ks*8 + (lane&3);
                    b[nt][0] = p[0];
                    b[nt][1] = p[4];
                } else {
                    const unsigned* p = sB[st] + (ks*8 + (lane&3))*BSTN + wc*32 + nt*8 + (lane>>2);
                    b[nt][0] = p[0];
                    b[nt][1] = p[4*BSTN];
                }
            }
            #pragma unroll
            for (int mt = 0; mt < 4; mt++)
                #pragma unroll
                for (int nt = 0; nt < 4; nt++)
                    mma_tf32(acc[mt][nt], a[mt], b[nt]);
        }
        __syncthreads();
    }

    #pragma unroll
    for (int mt = 0; mt < 4; mt++) {
        int row = m0 + wr*64 + mt*16 + (lane>>2);
        #pragma unroll
        for (int nt = 0; nt < 4; nt++) {
            int col = n0 + wc*32 + nt*8 + 2*(lane&3);
            *(float2*)&C[(size_t)row*N + col]     = make_float2(acc[mt][nt][0], acc[mt][nt][1]);
            *(float2*)&C[(size_t)(row+8)*N + col] = make_float2(acc[mt][nt][2], acc[mt][nt][3]);
        }
    }
}

// ---------------- bias dot tables ----------------
__global__ void rwk_kernel(const float* __restrict__ rw)
{
    int idx = blockIdx.x*blockDim.x + threadIdx.x;
    int j = idx & (KLEN-1);
    int bn = idx >> 10;
    int b = bn >> 4, n = bn & 15;
    const float* krow = &g_k[((size_t)j*BATCH + b)*DMODEL + n*DHEAD];
    const float* w = &rw[n*DHEAD];
    float s = 0.f;
    #pragma unroll 16
    for (int d = 0; d < DHEAD; d++) s += w[d]*krow[d];
    g_rwk[idx] = s;
}

__global__ void rrkr_kernel(const float* __restrict__ rr)
{
    int idx = blockIdx.x*blockDim.x + threadIdx.x;
    int jr = idx % RLEN;
    int bn = idx / RLEN;
    int b = bn >> 4, n = bn & 15;
    const float* krow = &g_kr[((size_t)jr*BATCH + b)*DMODEL + n*DHEAD];
    const float* w = &rr[n*DHEAD];
    float s = 0.f;
    #pragma unroll 16
    for (int d = 0; d < DHEAD; d++) s += w[d]*krow[d];
    g_rrkr[idx] = s;
}

__global__ void e_kernel(const float* __restrict__ rs, const float* __restrict__ seg)
{
    int idx = blockIdx.x*blockDim.x + threadIdx.x;
    int n = idx & 15;
    int ib = idx >> 4;
    int b = ib & 3, i = ib >> 2;
    const float* q = &g_q[((size_t)i*BATCH + b)*DMODEL + n*DHEAD];
    const float* w = &rs[n*DHEAD];
    const float* s0p = &seg[(0*NHEAD + n)*DHEAD];
    const float* s1p = &seg[(1*NHEAD + n)*DHEAD];
    float s0 = 0.f, s1 = 0.f;
    #pragma unroll 16
    for (int d = 0; d < DHEAD; d++) {
        float qr = q[d] + w[d];
        s0 += qr*s0p[d];
        s1 += qr*s1p[d];
    }
    g_e[idx*2+0] = s0;
    g_e[idx*2+1] = s1;
}

// ---------------- scores ----------------
__global__ __launch_bounds__(256) void score_kernel(const float* __restrict__ seg_mat,
                                                    const float* __restrict__ attn_mask)
{
    extern __shared__ float smf[];
    const int ST = 68;
    float* Qs  = smf;
    float* Ks  = smf + 64*ST;
    float* Krs = smf + 128*ST;
    const int bn = blockIdx.z, b = bn >> 4, n = bn & 15;
    const int i0 = blockIdx.y << 6, j0 = blockIdx.x << 6;
    const int krbase = j0 + 512 - i0 - 63;
    const int tid = threadIdx.x, tx = tid & 15, ty = tid >> 4;
    const int cbase = n*DHEAD;

    for (int t = tid; t < 64*16; t += 256) {
        int rrow = t >> 4, c4 = (t & 15) * 4;
        *(float4*)&Qs[rrow*ST + c4] =
            *(const float4*)&g_q[((size_t)(i0+rrow)*BATCH + b)*DMODEL + cbase + c4];
        *(float4*)&Ks[rrow*ST + c4] =
            *(const float4*)&g_k[((size_t)(j0+rrow)*BATCH + b)*DMODEL + cbase + c4];
    }
    for (int t = tid; t < 128*16; t += 256) {
        int rrow = t >> 4, c4 = (t & 15) * 4;
        int jr = krbase + rrow; if (jr > RLEN-1) jr = RLEN-1;
        *(float4*)&Krs[rrow*ST + c4] =
            *(const float4*)&g_kr[((size_t)jr*BATCH + b)*DMODEL + cbase + c4];
    }
    __syncthreads();

    float acc[4][4] = {};
    const int qrow = ty*4, kcol = tx*4;
    const int dbase = kcol - qrow + 60;

    #pragma unroll 4
    for (int d = 0; d < DHEAD; d++) {
        float qv[4], kv[4], krv[7];
        #pragma unroll
        for (int u = 0; u < 4; u++) qv[u] = Qs[(qrow+u)*ST + d];
        #pragma unroll
        for (int u = 0; u < 4; u++) kv[u] = Ks[(kcol+u)*ST + d];
        #pragma unroll
        for (int t = 0; t < 7; t++) krv[t] = Krs[(dbase+t)*ST + d];
        #pragma unroll
        for (int ii = 0; ii < 4; ii++)
            #pragma unroll
            for (int jj = 0; jj < 4; jj++)
                acc[ii][jj] += qv[ii]*(kv[jj] + krv[jj-ii+3]);
    }

    const float* rwk  = &g_rwk[bn*KLEN];
    const float* rrkr = &g_rrkr[bn*RLEN];
    #pragma unroll
    for (int ii = 0; ii < 4; ii++) {
        int i = i0 + qrow + ii;
        float e0 = g_e[(((size_t)i*BATCH + b)*NHEAD + n)*2 + 0];
        float e1 = g_e[(((size_t)i*BATCH + b)*NHEAD + n)*2 + 1];
        #pragma unroll
        for (int jj = 0; jj < 4; jj++) {
            int j = j0 + kcol + jj;
            int jr = j + 512 - i;
            size_t mi = ((size_t)i*KLEN + j)*BATCH + b;
            float sm0 = seg_mat[mi*2+0], sm1 = seg_mat[mi*2+1];
            float sc = (acc[ii][jj] + rwk[j] + rrkr[jr] + sm0*e0 + sm1*e1) * SCALE_F
                       - 1e30f * attn_mask[mi];
            g_scores[((size_t)bn*QLEN + i)*KLEN + j] = sc;
        }
    }
}

// ---------------- softmax ----------------
__global__ __launch_bounds__(256) void softmax_kernel()
{
    __shared__ float red[8];
    __shared__ float bcast;
    float* p = &g_scores[(size_t)blockIdx.x * KLEN];
    const int tid = threadIdx.x;
    float4 v = ((float4*)p)[tid];

    float m = fmaxf(fmaxf(v.x, v.y), fmaxf(v.z, v.w));
    #pragma unroll
    for (int o = 16; o; o >>= 1) m = fmaxf(m, __shfl_xor_sync(0xffffffffu, m, o));
    if ((tid & 31) == 0) red[tid >> 5] = m;
    __syncthreads();
    if (tid < 32) {
        float t = (tid < 8) ? red[tid] : -INFINITY;
        #pragma unroll
        for (int o = 4; o; o >>= 1) t = fmaxf(t, __shfl_xor_sync(0xffffffffu, t, o));
        if (tid == 0) bcast = t;
    }
    __syncthreads();
    m = bcast;
    __syncthreads();

    v.x = __expf(v.x - m); v.y = __expf(v.y - m);
    v.z = __expf(v.z - m); v.w = __expf(v.w - m);
    float s = v.x + v.y + v.z + v.w;
    #pragma unroll
    for (int o = 16; o; o >>= 1) s += __shfl_xor_sync(0xffffffffu, s, o);
    if ((tid & 31) == 0) red[tid >> 5] = s;
    __syncthreads();
    if (tid < 32) {
        float t = (tid < 8) ? red[tid] : 0.f;
        #pragma unroll
        for (int o = 4; o; o >>= 1) t += __shfl_xor_sync(0xffffffffu, t, o);
        if (tid == 0) bcast = 1.0f / t;
    }
    __syncthreads();
    float inv = bcast;
    v.x *= inv; v.y *= inv; v.z *= inv; v.w *= inv;
    ((float4*)p)[tid] = v;
}

// ---------------- attn_vec = prob @ v ----------------
__global__ __launch_bounds__(256) void pv_kernel()
{
    __shared__ float Ps[64][68];
    __shared__ float Vs[64][68];
    const int bn = blockIdx.y, b = bn >> 4, n = bn & 15;
    const int i0 = blockIdx.x << 6;
    const int tid = threadIdx.x, tx = tid & 15, ty = tid >> 4;
    float acc[4][4] = {};
    for (int j0 = 0; j0 < KLEN; j0 += 64) {
        for (int t = tid; t < 64*16; t += 256) {
            int rrow = t >> 4, c4 = (t & 15) * 4;
            *(float4*)&Ps[rrow][c4] =
                *(const float4*)&g_scores[((size_t)bn*QLEN + i0 + rrow)*KLEN + j0 + c4];
            *(float4*)&Vs[rrow][c4] =
                *(const float4*)&g_v[((size_t)(j0+rrow)*BATCH + b)*DMODEL + n*DHEAD + c4];
        }
        __syncthreads();
        #pragma unroll 8
        for (int jj = 0; jj < 64; jj++) {
            float pv[4], vv[4];
            #pragma unroll
            for (int u = 0; u < 4; u++) pv[u] = Ps[ty*4+u][jj];
            #pragma unroll
            for (int u = 0; u < 4; u++) vv[u] = Vs[jj][tx*4+u];
            #pragma unroll
            for (int ii = 0; ii < 4; ii++)
                #pragma unroll
                for (int dd = 0; dd < 4; dd++)
                    acc[ii][dd] += pv[ii]*vv[dd];
        }
        __syncthreads();
    }
    #pragma unroll
    for (int ii = 0; ii < 4; ii++)
        *(float4*)&g_vec[((size_t)(i0+ty*4+ii)*BATCH + b)*DMODEL + n*DHEAD + tx*4] =
            *(float4*)&acc[ii][0];
}

// ---------------- out = layer_norm(attn_out + h) ----------------
__global__ __launch_bounds__(256) void addln_kernel(const float* __restrict__ h,
                                                    const float* __restrict__ gamma,
                                                    const float* __restrict__ beta,
                                                    float* __restrict__ out)
{
    __shared__ float red[8];
    __shared__ float bc;
    const int row = blockIdx.x;
    const int tid = threadIdx.x;
    float4 x  = ((const float4*)&g_att[(size_t)row*DMODEL])[tid];
    float4 hh = ((const float4*)&h[(size_t)row*DMODEL])[tid];
    x.x += hh.x; x.y += hh.y; x.z += hh.z; x.w += hh.w;

    float s = x.x + x.y + x.z + x.w;
    #pragma unroll
    for (int o = 16; o; o >>= 1) s += __shfl_xor_sync(0xffffffffu, s, o);
    if ((tid & 31) == 0) red[tid >> 5] = s;
    __syncthreads();
    if (tid < 32) {
        float t = (tid < 8) ? red[tid] : 0.f;
        #pragma unroll
        for (int o = 4; o; o >>= 1) t += __shfl_xor_sync(0xffffffffu, t, o);
        if (tid == 0) bc = t * (1.0f/DMODEL);
    }
    __syncthreads();
    float mu = bc;
    __syncthreads();

    float dx0 = x.x - mu, dx1 = x.y - mu, dx2 = x.z - mu, dx3 = x.w - mu;
    float sq = dx0*dx0 + dx1*dx1 + dx2*dx2 + dx3*dx3;
    #pragma unroll
    for (int o = 16; o; o >>= 1) sq += __shfl_xor_sync(0xffffffffu, sq, o);
    if ((tid & 31) == 0) red[tid >> 5] = sq;
    __syncthreads();
    if (tid < 32) {
        float t = (tid < 8) ? red[tid] : 0.f;
        #pragma unroll
        for (int o = 4; o; o >>= 1) t += __shfl_xor_sync(0xffffffffu, t, o);
        if (tid == 0) bc = rsqrtf(t * (1.0f/DMODEL) + LN_EPS);
    }
    __syncthreads();
    float inv = bc;

    float4 g = ((const float4*)gamma)[tid];
    float4 bt = ((const float4*)beta)[tid];
    float4 o4;
    o4.x = dx0*inv*g.x + bt.x;
    o4.y = dx1*inv*g.y + bt.y;
    o4.z = dx2*inv*g.z + bt.z;
    o4.w = dx3*inv*g.w + bt.w;
    ((float4*)&out[(size_t)row*DMODEL])[tid] = o4;
}

// ---------------- launch ----------------
extern "C" void kernel_launch(void* const* d_in, const int* in_sizes, int n_in,
                              void* d_out, int out_size)
{
    (void)in_sizes; (void)n_in; (void)out_size;
    const float* rw        = (const float*)d_in[0];
    const float* rs        = (const float*)d_in[1];
    const float* rr        = (const float*)d_in[2];
    const float* seg_embed = (const float*)d_in[3];
    const float* h         = (const float*)d_in[4];
    const float* r         = (const float*)d_in[5];
    const float* mems      = (const float*)d_in[6];
    const float* seg_mat   = (const float*)d_in[7];
    const float* attn_mask = (const float*)d_in[8];
    const float* wq        = (const float*)d_in[9];
    const float* wk        = (const float*)d_in[10];
    const float* wv        = (const float*)d_in[11];
    const float* wr        = (const float*)d_in[12];
    const float* wo        = (const float*)d_in[13];
    const float* gamma     = (const float*)d_in[14];
    const float* beta      = (const float*)d_in[15];

    void *p_q, *p_k, *p_v, *p_kr, *p_vec, *p_att;
    void *p_ht, *p_catt, *p_rt, *p_wqt, *p_wkt, *p_wvt, *p_wrt, *p_wot, *p_vect;
    cudaGetSymbolAddress(&p_q,   g_q);
    cudaGetSymbolAddress(&p_k,   g_k);
    cudaGetSymbolAddress(&p_v,   g_v);
    cudaGetSymbolAddress(&p_kr,  g_kr);
    cudaGetSymbolAddress(&p_vec, g_vec);
    cudaGetSymbolAddress(&p_att, g_att);
    cudaGetSymbolAddress(&p_ht,  g_ht);
    cudaGetSymbolAddress(&p_catt,g_catt);
    cudaGetSymbolAddress(&p_rt,  g_rt);
    cudaGetSymbolAddress(&p_wqt, g_wqt);
    cudaGetSymbolAddress(&p_wkt, g_wkt);
    cudaGetSymbolAddress(&p_wvt, g_wvt);
    cudaGetSymbolAddress(&p_wrt, g_wrt);
    cudaGetSymbolAddress(&p_wot, g_wot);
    cudaGetSymbolAddress(&p_vect,g_vect);

    // tf32 conversions (concat fused into g_catt)
    const int HN = QLEN*BATCH*DMODEL;   // 2M elems
    const int WN = DMODEL*DMODEL;       // 1M elems
    cvt_tf32<<<HN/1024, 256>>>(h,    (unsigned*)p_ht);
    cvt_tf32<<<HN/1024, 256>>>(mems, (unsigned*)p_catt);
    cvt_tf32<<<HN/1024, 256>>>(h,    (unsigned*)p_catt + (size_t)MLEN*BATCH*DMODEL);
    cvt_tf32<<<RLEN*BATCH*DMODEL/1024, 256>>>(r, (unsigned*)p_rt);
    cvt_tf32<<<WN/1024, 256>>>(wq, (unsigned*)p_wqt);
    cvt_tf32<<<WN/1024, 256>>>(wk, (unsigned*)p_wkt);
    cvt_tf32<<<WN/1024, 256>>>(wv, (unsigned*)p_wvt);
    cvt_tf32<<<WN/1024, 256>>>(wr, (unsigned*)p_wrt);
    cvt_tf32<<<WN/1024, 256>>>(wo, (unsigned*)p_wot);

    // tensor-core projections
    const int SMEM_NN = 2*(128*AST + 32*BSTN)*4;
    const int SMEM_NT = 2*(128*AST + 128*BSTT)*4;
    cudaFuncSetAttribute(gemm_tf32<0>, cudaFuncAttributeMaxDynamicSharedMemorySize, SMEM_NN);
    cudaFuncSetAttribute(gemm_tf32<1>, cudaFuncAttributeMaxDynamicSharedMemorySize, SMEM_NT);
    gemm_tf32<0><<<dim3(8,16), 256, SMEM_NN>>>((unsigned*)p_ht,   (unsigned*)p_wqt, (float*)p_q,  QLEN*BATCH);
    gemm_tf32<0><<<dim3(8,32), 256, SMEM_NN>>>((unsigned*)p_catt, (unsigned*)p_wkt, (float*)p_k,  KLEN*BATCH);
    gemm_tf32<0><<<dim3(8,32), 256, SMEM_NN>>>((unsigned*)p_catt, (unsigned*)p_wvt, (float*)p_v,  KLEN*BATCH);
    gemm_tf32<0><<<dim3(8,48), 256, SMEM_NN>>>((unsigned*)p_rt,   (unsigned*)p_wrt, (float*)p_kr, RLEN*BATCH);

    // bias dot tables
    rwk_kernel<<<BN_TOT*KLEN/256, 256>>>(rw);
    rrkr_kernel<<<BN_TOT*RLEN/256, 256>>>(rr);
    e_kernel<<<QLEN*BATCH*NHEAD/256, 256>>>(rs, seg_embed);

    // scores
    cudaFuncSetAttribute(score_kernel, cudaFuncAttributeMaxDynamicSharedMemorySize, 256*68*4);
    score_kernel<<<dim3(16,8,64), 256, 256*68*4>>>(seg_mat, attn_mask);

    // softmax
    softmax_kernel<<<BN_TOT*QLEN, 256>>>();

    // attn_vec
    pv_kernel<<<dim3(8,64), 256>>>();

    // attn_out = vec @ wo^T  (tensor core, nt)
    cvt_tf32<<<HN/1024, 256>>>((float*)p_vec, (unsigned*)p_vect);
    gemm_tf32<1><<<dim3(8,16), 256, SMEM_NT>>>((unsigned*)p_vect, (unsigned*)p_wot, (float*)p_att, QLEN*BATCH);

    // layernorm(attn_out + h)
    addln_kernel<<<QLEN*BATCH, 256>>>(h, gamma, beta, (float*)d_out);
}

// round 6
// speedup vs baseline: 2.4814x; 1.7466x over previous
#include <cuda_runtime.h>
#include <math.h>
#include <stdint.h>

#define QLEN   512
#define MLEN   512
#define KLEN   1024
#define RLEN   1536
#define BATCH  4
#define DMODEL 1024
#define NHEAD  16
#define DHEAD  64
#define BN_TOT (BATCH*NHEAD)
#define SCALE_F 0.125f
#define LN_EPS 1e-3f

// ---------------- scratch (device globals; no allocation allowed) ----------------
__device__ float g_q  [(size_t)QLEN*BATCH*DMODEL];     // tf32-rounded
__device__ float g_k  [(size_t)KLEN*BATCH*DMODEL];     // tf32-rounded
__device__ float g_v  [(size_t)KLEN*BATCH*DMODEL];     // tf32-rounded
__device__ float g_kr [(size_t)RLEN*BATCH*DMODEL];     // tf32-rounded
__device__ float g_e  [QLEN*BATCH*NHEAD*2];
__device__ float g_rwk [BN_TOT*KLEN];
__device__ float g_rrkr[BN_TOT*RLEN];
__device__ float g_ac [(size_t)BN_TOT*QLEN*KLEN];      // 128 MB
__device__ float g_bd [(size_t)BN_TOT*QLEN*RLEN];      // 192 MB
__device__ float g_scores[(size_t)BN_TOT*QLEN*KLEN];   // probs (tf32 bits), 128 MB
__device__ float g_vec[(size_t)QLEN*BATCH*DMODEL];     // tf32-rounded
__device__ float g_att[(size_t)QLEN*BATCH*DMODEL];

// tf32-converted inputs
__device__ unsigned g_ht  [(size_t)QLEN*BATCH*DMODEL];
__device__ unsigned g_catt[(size_t)KLEN*BATCH*DMODEL];
__device__ unsigned g_rt  [(size_t)RLEN*BATCH*DMODEL];
__device__ unsigned g_wqt [DMODEL*DMODEL];
__device__ unsigned g_wkt [DMODEL*DMODEL];
__device__ unsigned g_wvt [DMODEL*DMODEL];
__device__ unsigned g_wrt [DMODEL*DMODEL];
__device__ unsigned g_wot [DMODEL*DMODEL];

// ---------------- helpers ----------------
__device__ __forceinline__ unsigned f2tf(float f) {
    unsigned u;
    asm("cvt.rna.tf32.f32 %0, %1;" : "=r"(u) : "f"(f));
    return u;
}
__device__ __forceinline__ void cp16(void* dst, const void* src) {
    unsigned d = (unsigned)__cvta_generic_to_shared(dst);
    asm volatile("cp.async.cg.shared.global [%0], [%1], 16;" :: "r"(d), "l"(src));
}
__device__ __forceinline__ void mma_tf32(float* c, const unsigned* a, const unsigned* b) {
    asm volatile("mma.sync.aligned.m16n8k8.row.col.f32.tf32.tf32.f32 "
                 "{%0,%1,%2,%3}, {%4,%5,%6,%7}, {%8,%9}, {%0,%1,%2,%3};"
                 : "+f"(c[0]), "+f"(c[1]), "+f"(c[2]), "+f"(c[3])
                 : "r"(a[0]), "r"(a[1]), "r"(a[2]), "r"(a[3]), "r"(b[0]), "r"(b[1]));
}

__global__ __launch_bounds__(256) void cvt_tf32(const float* __restrict__ in,
                                                unsigned* __restrict__ out)
{
    int i = blockIdx.x*256 + threadIdx.x;
    float4 v = ((const float4*)in)[i];
    uint4 o;
    o.x = f2tf(v.x); o.y = f2tf(v.y); o.z = f2tf(v.z); o.w = f2tf(v.w);
    ((uint4*)out)[i] = o;
}

// ---------------- tf32 tensor-core GEMM (projections / output proj) ----------------
#define AST 36
#define BSTN 132
#define BSTT 36

template<int NT, int RND>
__global__ __launch_bounds__(256, 2) void gemm_tf32(const unsigned* __restrict__ A,
                                                    const unsigned* __restrict__ B,
                                                    float* __restrict__ C, int M)
{
    constexpr int N = 1024, K = 1024;
    constexpr int ASZ = 128*AST;
    constexpr int BSZ = NT ? 128*BSTT : 32*BSTN;
    constexpr int NIT = K/32;
    extern __shared__ unsigned sm[];
    unsigned* sA[2] = { sm,        sm + ASZ + BSZ };
    unsigned* sB[2] = { sm + ASZ,  sm + 2*ASZ + BSZ };

    const int tid = threadIdx.x;
    const int m0 = blockIdx.y << 7;
    const int n0 = blockIdx.x << 7;
    const int lane = tid & 31, wid = tid >> 5;
    const int wr = wid >> 2, wc = wid & 3;

    float acc[4][4][4] = {};

    auto issue = [&](int it, int st) {
        int k0 = it * 32;
        #pragma unroll
        for (int q = 0; q < 4; q++) {
            int idx = tid + 256*q;
            int row = idx >> 3, kc = (idx & 7) * 4;
            cp16(&sA[st][row*AST + kc], &A[(size_t)(m0+row)*K + k0 + kc]);
        }
        if (NT) {
            #pragma unroll
            for (int q = 0; q < 4; q++) {
                int idx = tid + 256*q;
                int row = idx >> 3, kc = (idx & 7) * 4;
                cp16(&sB[st][row*BSTT + kc], &B[(size_t)(n0+row)*K + k0 + kc]);
            }
        } else {
            #pragma unroll
            for (int q = 0; q < 4; q++) {
                int idx = tid + 256*q;
                int row = idx >> 5, nc = (idx & 31) * 4;
                cp16(&sB[st][row*BSTN + nc], &B[(size_t)(k0+row)*N + n0 + nc]);
            }
        }
        asm volatile("cp.async.commit_group;");
    };

    issue(0, 0);
    for (int it = 0; it < NIT; it++) {
        int st = it & 1;
        if (it + 1 < NIT) issue(it+1, st^1);
        if (it + 1 < NIT) asm volatile("cp.async.wait_group 1;");
        else              asm volatile("cp.async.wait_group 0;");
        __syncthreads();

        const unsigned* Ab = sA[st] + (wr*64 + (lane>>2))*AST + (lane&3);
        #pragma unroll
        for (int ks = 0; ks < 4; ks++) {
            unsigned a[4][4];
            #pragma unroll
            for (int mt = 0; mt < 4; mt++) {
                const unsigned* p = Ab + mt*16*AST + ks*8;
                a[mt][0] = p[0];
                a[mt][1] = p[8*AST];
                a[mt][2] = p[4];
                a[mt][3] = p[8*AST + 4];
            }
            unsigned b[4][2];
            #pragma unroll
            for (int nt = 0; nt < 4; nt++) {
                if (NT) {
                    const unsigned* p = sB[st] + (wc*32 + nt*8 + (lane>>2))*BSTT + ks*8 + (lane&3);
                    b[nt][0] = p[0];
                    b[nt][1] = p[4];
                } else {
                    const unsigned* p = sB[st] + (ks*8 + (lane&3))*BSTN + wc*32 + nt*8 + (lane>>2);
                    b[nt][0] = p[0];
                    b[nt][1] = p[4*BSTN];
                }
            }
            #pragma unroll
            for (int mt = 0; mt < 4; mt++)
                #pragma unroll
                for (int nt = 0; nt < 4; nt++)
                    mma_tf32(acc[mt][nt], a[mt], b[nt]);
        }
        __syncthreads();
    }

    #pragma unroll
    for (int mt = 0; mt < 4; mt++) {
        int row = m0 + wr*64 + mt*16 + (lane>>2);
        #pragma unroll
        for (int nt = 0; nt < 4; nt++) {
            int col = n0 + wc*32 + nt*8 + 2*(lane&3);
            float v0 = acc[mt][nt][0], v1 = acc[mt][nt][1];
            float v2 = acc[mt][nt][2], v3 = acc[mt][nt][3];
            if (RND) {
                v0 = __uint_as_float(f2tf(v0)); v1 = __uint_as_float(f2tf(v1));
                v2 = __uint_as_float(f2tf(v2)); v3 = __uint_as_float(f2tf(v3));
            }
            *(float2*)&C[(size_t)row*N + col]     = make_float2(v0, v1);
            *(float2*)&C[(size_t)(row+8)*N + col] = make_float2(v2, v3);
        }
    }
}

// ---------------- batched per-head GEMM: C[bn] = A_head @ B_head^T, K=64 ----------------
__global__ __launch_bounds__(256, 2) void head_gemm(const unsigned* __restrict__ A,
                                                    const unsigned* __restrict__ Bm,
                                                    float* __restrict__ C, int Ntot)
{
    extern __shared__ unsigned sm[];
    unsigned* sA = sm;             // 128 x 68
    unsigned* sB = sm + 128*68;    // 128 x 68
    const int bn = blockIdx.z, b = bn >> 4, n = bn & 15;
    const int i0 = blockIdx.y << 7, j0 = blockIdx.x << 7;
    const int tid = threadIdx.x, lane = tid & 31, wid = tid >> 5;
    const int wr = wid >> 2, wc = wid & 3;
    const size_t hoff = (size_t)b*DMODEL + n*DHEAD;

    #pragma unroll
    for (int q = 0; q < 8; q++) {
        int idx = tid + 256*q;
        int row = idx >> 4, kc = (idx & 15) * 4;
        cp16(&sA[row*68 + kc], &A[(size_t)(i0+row)*(BATCH*DMODEL) + hoff + kc]);
    }
    #pragma unroll
    for (int q = 0; q < 8; q++) {
        int idx = tid + 256*q;
        int row = idx >> 4, kc = (idx & 15) * 4;
        cp16(&sB[row*68 + kc], &Bm[(size_t)(j0+row)*(BATCH*DMODEL) + hoff + kc]);
    }
    asm volatile("cp.async.commit_group;\n\tcp.async.wait_group 0;");
    __syncthreads();

    float acc[4][4][4] = {};
    const unsigned* Ab = sA + (wr*64 + (lane>>2))*68 + (lane&3);
    #pragma unroll
    for (int ks = 0; ks < 8; ks++) {
        unsigned a[4][4];
        #pragma unroll
        for (int mt = 0; mt < 4; mt++) {
            const unsigned* p = Ab + mt*16*68 + ks*8;
            a[mt][0] = p[0];
            a[mt][1] = p[8*68];
            a[mt][2] = p[4];
            a[mt][3] = p[8*68 + 4];
        }
        unsigned bf[4][2];
        #pragma unroll
        for (int nt = 0; nt < 4; nt++) {
            const unsigned* p = sB + (wc*32 + nt*8 + (lane>>2))*68 + ks*8 + (lane&3);
            bf[nt][0] = p[0];
            bf[nt][1] = p[4];
        }
        #pragma unroll
        for (int mt = 0; mt < 4; mt++)
            #pragma unroll
            for (int nt = 0; nt < 4; nt++)
                mma_tf32(acc[mt][nt], a[mt], bf[nt]);
    }

    #pragma unroll
    for (int mt = 0; mt < 4; mt++) {
        int row = i0 + wr*64 + mt*16 + (lane>>2);
        #pragma unroll
        for (int nt = 0; nt < 4; nt++) {
            int col = j0 + wc*32 + nt*8 + 2*(lane&3);
            *(float2*)&C[((size_t)bn*QLEN + row)*Ntot + col] =
                make_float2(acc[mt][nt][0], acc[mt][nt][1]);
            *(float2*)&C[((size_t)bn*QLEN + row + 8)*Ntot + col] =
                make_float2(acc[mt][nt][2], acc[mt][nt][3]);
        }
    }
}

// ---------------- bias dot tables ----------------
__global__ void rwk_kernel(const float* __restrict__ rw)
{
    int idx = blockIdx.x*blockDim.x + threadIdx.x;
    int j = idx & (KLEN-1);
    int bn = idx >> 10;
    int b = bn >> 4, n = bn & 15;
    const float* krow = &g_k[((size_t)j*BATCH + b)*DMODEL + n*DHEAD];
    const float* w = &rw[n*DHEAD];
    float s = 0.f;
    #pragma unroll 16
    for (int d = 0; d < DHEAD; d++) s += w[d]*krow[d];
    g_rwk[idx] = s;
}

__global__ void rrkr_kernel(const float* __restrict__ rr)
{
    int idx = blockIdx.x*blockDim.x + threadIdx.x;
    int jr = idx % RLEN;
    int bn = idx / RLEN;
    int b = bn >> 4, n = bn & 15;
    const float* krow = &g_kr[((size_t)jr*BATCH + b)*DMODEL + n*DHEAD];
    const float* w = &rr[n*DHEAD];
    float s = 0.f;
    #pragma unroll 16
    for (int d = 0; d < DHEAD; d++) s += w[d]*krow[d];
    g_rrkr[idx] = s;
}

__global__ void e_kernel(const float* __restrict__ rs, const float* __restrict__ seg)
{
    int idx = blockIdx.x*blockDim.x + threadIdx.x;
    int n = idx & 15;
    int ib = idx >> 4;
    int b = ib & 3, i = ib >> 2;
    const float* q = &g_q[((size_t)i*BATCH + b)*DMODEL + n*DHEAD];
    const float* w = &rs[n*DHEAD];
    const float* s0p = &seg[(0*NHEAD + n)*DHEAD];
    const float* s1p = &seg[(1*NHEAD + n)*DHEAD];
    float s0 = 0.f, s1 = 0.f;
    #pragma unroll 16
    for (int d = 0; d < DHEAD; d++) {
        float qr = q[d] + w[d];
        s0 += qr*s0p[d];
        s1 += qr*s1p[d];
    }
    g_e[idx*2+0] = s0;
    g_e[idx*2+1] = s1;
}

// ---------------- fused score assembly + softmax; writes tf32 probs ----------------
__global__ __launch_bounds__(256) void score_softmax(const float* __restrict__ seg_mat,
                                                     const float* __restrict__ attn_mask)
{
    __shared__ float red[8];
    __shared__ float bcast;
    const int i = blockIdx.x, bn = blockIdx.y;
    const int b = bn >> 4, n = bn & 15;
    const int tid = threadIdx.x;
    const int j = tid * 4;
    const size_t rowid = (size_t)bn*QLEN + i;
    const int shift = 512 - i;

    const float* ac   = &g_ac[rowid*KLEN];
    const float* bd   = &g_bd[rowid*RLEN + shift];
    const float* rwk  = &g_rwk[bn*KLEN];
    const float* rrkr = &g_rrkr[(size_t)bn*RLEN + shift];
    const float  e0   = g_e[(((size_t)i*BATCH + b)*NHEAD + n)*2 + 0];
    const float  e1   = g_e[(((size_t)i*BATCH + b)*NHEAD + n)*2 + 1];

    float4 acv  = ((const float4*)ac)[tid];
    float4 rwkv = ((const float4*)rwk)[tid];
    float sc[4];
    #pragma unroll
    for (int u = 0; u < 4; u++) {
        int jj = j + u;
        size_t mi = ((size_t)i*KLEN + jj)*BATCH + b;
        float a = (u==0)?acv.x:(u==1)?acv.y:(u==2)?acv.z:acv.w;
        float rk = (u==0)?rwkv.x:(u==1)?rwkv.y:(u==2)?rwkv.z:rwkv.w;
        float s = a + bd[jj] + rk + rrkr[jj]
                + seg_mat[mi*2+0]*e0 + seg_mat[mi*2+1]*e1;
        sc[u] = s * SCALE_F - 1e30f * attn_mask[mi];
    }

    float m = fmaxf(fmaxf(sc[0], sc[1]), fmaxf(sc[2], sc[3]));
    #pragma unroll
    for (int o = 16; o; o >>= 1) m = fmaxf(m, __shfl_xor_sync(0xffffffffu, m, o));
    if ((tid & 31) == 0) red[tid >> 5] = m;
    __syncthreads();
    if (tid < 32) {
        float t = (tid < 8) ? red[tid] : -INFINITY;
        #pragma unroll
        for (int o = 4; o; o >>= 1) t = fmaxf(t, __shfl_xor_sync(0xffffffffu, t, o));
        if (tid == 0) bcast = t;
    }
    __syncthreads();
    m = bcast;
    __syncthreads();

    float ssum = 0.f;
    #pragma unroll
    for (int u = 0; u < 4; u++) { sc[u] = __expf(sc[u] - m); ssum += sc[u]; }
    #pragma unroll
    for (int o = 16; o; o >>= 1) ssum += __shfl_xor_sync(0xffffffffu, ssum, o);
    if ((tid & 31) == 0) red[tid >> 5] = ssum;
    __syncthreads();
    if (tid < 32) {
        float t = (tid < 8) ? red[tid] : 0.f;
        #pragma unroll
        for (int o = 4; o; o >>= 1) t += __shfl_xor_sync(0xffffffffu, t, o);
        if (tid == 0) bcast = 1.0f / t;
    }
    __syncthreads();
    float inv = bcast;

    uint4 o4;
    o4.x = f2tf(sc[0]*inv); o4.y = f2tf(sc[1]*inv);
    o4.z = f2tf(sc[2]*inv); o4.w = f2tf(sc[3]*inv);
    ((uint4*)&g_scores[rowid*KLEN])[tid] = o4;
}

// ---------------- PV on tensor cores: vec[bn] = P[512,1024] @ V[1024,64] ----------------
__global__ __launch_bounds__(256, 2) void pv_mma()
{
    extern __shared__ unsigned sm[];
    unsigned* sP[2] = { sm,            sm + 128*36 + 32*68 };
    unsigned* sV[2] = { sm + 128*36,   sm + 2*(128*36) + 32*68 };
    const int bn = blockIdx.y, b = bn >> 4, n = bn & 15;
    const int i0 = blockIdx.x << 7;
    const int tid = threadIdx.x, lane = tid & 31, wid = tid >> 5;
    const int wr = wid >> 1, wc = wid & 1;
    const unsigned* P = (const unsigned*)g_scores;
    const unsigned* V = (const unsigned*)g_v;

    auto issue = [&](int it, int st) {
        int k0 = it * 32;
        #pragma unroll
        for (int q = 0; q < 4; q++) {
            int idx = tid + 256*q;
            int row = idx >> 3, kc = (idx & 7) * 4;
            cp16(&sP[st][row*36 + kc], &P[((size_t)bn*QLEN + i0 + row)*KLEN + k0 + kc]);
        }
        #pragma unroll
        for (int q = 0; q < 2; q++) {
            int idx = tid + 256*q;
            int row = idx >> 4, c4 = (idx & 15) * 4;
            cp16(&sV[st][row*68 + c4], &V[(size_t)(k0+row)*(BATCH*DMODEL) + (size_t)b*DMODEL + n*DHEAD + c4]);
        }
        asm volatile("cp.async.commit_group;");
    };

    float acc[2][4][4] = {};
    issue(0, 0);
    for (int it = 0; it < 32; it++) {
        int st = it & 1;
        if (it + 1 < 32) issue(it+1, st^1);
        if (it + 1 < 32) asm volatile("cp.async.wait_group 1;");
        else             asm volatile("cp.async.wait_group 0;");
        __syncthreads();

        const unsigned* Ab = sP[st] + (wr*32 + (lane>>2))*36 + (lane&3);
        #pragma unroll
        for (int ks = 0; ks < 4; ks++) {
            unsigned a[2][4];
            #pragma unroll
            for (int mt = 0; mt < 2; mt++) {
                const unsigned* p = Ab + mt*16*36 + ks*8;
                a[mt][0] = p[0];
                a[mt][1] = p[8*36];
                a[mt][2] = p[4];
                a[mt][3] = p[8*36 + 4];
            }
            unsigned bf[4][2];
            #pragma unroll
            for (int nt = 0; nt < 4; nt++) {
                const unsigned* p = sV[st] + (ks*8 + (lane&3))*68 + wc*32 + nt*8 + (lane>>2);
                bf[nt][0] = p[0];
                bf[nt][1] = p[4*68];
            }
            #pragma unroll
            for (int mt = 0; mt < 2; mt++)
                #pragma unroll
                for (int nt = 0; nt < 4; nt++)
                    mma_tf32(acc[mt][nt], a[mt], bf[nt]);
        }
        __syncthreads();
    }

    #pragma unroll
    for (int mt = 0; mt < 2; mt++) {
        int row = i0 + wr*32 + mt*16 + (lane>>2);
        #pragma unroll
        for (int nt = 0; nt < 4; nt++) {
            int col = wc*32 + nt*8 + 2*(lane&3);
            float2 lo = make_float2(__uint_as_float(f2tf(acc[mt][nt][0])),
                                    __uint_as_float(f2tf(acc[mt][nt][1])));
            float2 hi = make_float2(__uint_as_float(f2tf(acc[mt][nt][2])),
                                    __uint_as_float(f2tf(acc[mt][nt][3])));
            *(float2*)&g_vec[((size_t)row*BATCH + b)*DMODEL + n*DHEAD + col]     = lo;
            *(float2*)&g_vec[((size_t)(row+8)*BATCH + b)*DMODEL + n*DHEAD + col] = hi;
        }
    }
}

// ---------------- out = layer_norm(attn_out + h) ----------------
__global__ __launch_bounds__(256) void addln_kernel(const float* __restrict__ h,
                                                    const float* __restrict__ gamma,
                                                    const float* __restrict__ beta,
                                                    float* __restrict__ out)
{
    __shared__ float red[8];
    __shared__ float bc;
    const int row = blockIdx.x;
    const int tid = threadIdx.x;
    float4 x  = ((const float4*)&g_att[(size_t)row*DMODEL])[tid];
    float4 hh = ((const float4*)&h[(size_t)row*DMODEL])[tid];
    x.x += hh.x; x.y += hh.y; x.z += hh.z; x.w += hh.w;

    float s = x.x + x.y + x.z + x.w;
    #pragma unroll
    for (int o = 16; o; o >>= 1) s += __shfl_xor_sync(0xffffffffu, s, o);
    if ((tid & 31) == 0) red[tid >> 5] = s;
    __syncthreads();
    if (tid < 32) {
        float t = (tid < 8) ? red[tid] : 0.f;
        #pragma unroll
        for (int o = 4; o; o >>= 1) t += __shfl_xor_sync(0xffffffffu, t, o);
        if (tid == 0) bc = t * (1.0f/DMODEL);
    }
    __syncthreads();
    float mu = bc;
    __syncthreads();

    float dx0 = x.x - mu, dx1 = x.y - mu, dx2 = x.z - mu, dx3 = x.w - mu;
    float sq = dx0*dx0 + dx1*dx1 + dx2*dx2 + dx3*dx3;
    #pragma unroll
    for (int o = 16; o; o >>= 1) sq += __shfl_xor_sync(0xffffffffu, sq, o);
    if ((tid & 31) == 0) red[tid >> 5] = sq;
    __syncthreads();
    if (tid < 32) {
        float t = (tid < 8) ? red[tid] : 0.f;
        #pragma unroll
        for (int o = 4; o; o >>= 1) t += __shfl_xor_sync(0xffffffffu, t, o);
        if (tid == 0) bc = rsqrtf(t * (1.0f/DMODEL) + LN_EPS);
    }
    __syncthreads();
    float inv = bc;

    float4 g = ((const float4*)gamma)[tid];
    float4 bt = ((const float4*)beta)[tid];
    float4 o4;
    o4.x = dx0*inv*g.x + bt.x;
    o4.y = dx1*inv*g.y + bt.y;
    o4.z = dx2*inv*g.z + bt.z;
    o4.w = dx3*inv*g.w + bt.w;
    ((float4*)&out[(size_t)row*DMODEL])[tid] = o4;
}

// ---------------- launch ----------------
extern "C" void kernel_launch(void* const* d_in, const int* in_sizes, int n_in,
                              void* d_out, int out_size)
{
    (void)in_sizes; (void)n_in; (void)out_size;
    const float* rw        = (const float*)d_in[0];
    const float* rs        = (const float*)d_in[1];
    const float* rr        = (const float*)d_in[2];
    const float* seg_embed = (const float*)d_in[3];
    const float* h         = (const float*)d_in[4];
    const float* r         = (const float*)d_in[5];
    const float* mems      = (const float*)d_in[6];
    const float* seg_mat   = (const float*)d_in[7];
    const float* attn_mask = (const float*)d_in[8];
    const float* wq        = (const float*)d_in[9];
    const float* wk        = (const float*)d_in[10];
    const float* wv        = (const float*)d_in[11];
    const float* wr        = (const float*)d_in[12];
    const float* wo        = (const float*)d_in[13];
    const float* gamma     = (const float*)d_in[14];
    const float* beta      = (const float*)d_in[15];

    void *p_q, *p_k, *p_v, *p_kr, *p_vec, *p_att, *p_ac, *p_bd;
    void *p_ht, *p_catt, *p_rt, *p_wqt, *p_wkt, *p_wvt, *p_wrt, *p_wot;
    cudaGetSymbolAddress(&p_q,   g_q);
    cudaGetSymbolAddress(&p_k,   g_k);
    cudaGetSymbolAddress(&p_v,   g_v);
    cudaGetSymbolAddress(&p_kr,  g_kr);
    cudaGetSymbolAddress(&p_vec, g_vec);
    cudaGetSymbolAddress(&p_att, g_att);
    cudaGetSymbolAddress(&p_ac,  g_ac);
    cudaGetSymbolAddress(&p_bd,  g_bd);
    cudaGetSymbolAddress(&p_ht,  g_ht);
    cudaGetSymbolAddress(&p_catt,g_catt);
    cudaGetSymbolAddress(&p_rt,  g_rt);
    cudaGetSymbolAddress(&p_wqt, g_wqt);
    cudaGetSymbolAddress(&p_wkt, g_wkt);
    cudaGetSymbolAddress(&p_wvt, g_wvt);
    cudaGetSymbolAddress(&p_wrt, g_wrt);
    cudaGetSymbolAddress(&p_wot, g_wot);

    // tf32 conversions (concat fused into g_catt)
    const int HN = QLEN*BATCH*DMODEL;
    const int WN = DMODEL*DMODEL;
    cvt_tf32<<<HN/1024, 256>>>(h,    (unsigned*)p_ht);
    cvt_tf32<<<HN/1024, 256>>>(mems, (unsigned*)p_catt);
    cvt_tf32<<<HN/1024, 256>>>(h,    (unsigned*)p_catt + (size_t)MLEN*BATCH*DMODEL);
    cvt_tf32<<<RLEN*BATCH*DMODEL/1024, 256>>>(r, (unsigned*)p_rt);
    cvt_tf32<<<WN/1024, 256>>>(wq, (unsigned*)p_wqt);
    cvt_tf32<<<WN/1024, 256>>>(wk, (unsigned*)p_wkt);
    cvt_tf32<<<WN/1024, 256>>>(wv, (unsigned*)p_wvt);
    cvt_tf32<<<WN/1024, 256>>>(wr, (unsigned*)p_wrt);
    cvt_tf32<<<WN/1024, 256>>>(wo, (unsigned*)p_wot);

    // tensor-core projections (outputs tf32-rounded)
    const int SMEM_NN = 2*(128*AST + 32*BSTN)*4;
    const int SMEM_NT = 2*(128*AST + 128*BSTT)*4;
    cudaFuncSetAttribute((const void*)gemm_tf32<0,1>, cudaFuncAttributeMaxDynamicSharedMemorySize, SMEM_NN);
    cudaFuncSetAttribute((const void*)gemm_tf32<1,0>, cudaFuncAttributeMaxDynamicSharedMemorySize, SMEM_NT);
    gemm_tf32<0,1><<<dim3(8,16), 256, SMEM_NN>>>((unsigned*)p_ht,   (unsigned*)p_wqt, (float*)p_q,  QLEN*BATCH);
    gemm_tf32<0,1><<<dim3(8,32), 256, SMEM_NN>>>((unsigned*)p_catt, (unsigned*)p_wkt, (float*)p_k,  KLEN*BATCH);
    gemm_tf32<0,1><<<dim3(8,32), 256, SMEM_NN>>>((unsigned*)p_catt, (unsigned*)p_wvt, (float*)p_v,  KLEN*BATCH);
    gemm_tf32<0,1><<<dim3(8,48), 256, SMEM_NN>>>((unsigned*)p_rt,   (unsigned*)p_wrt, (float*)p_kr, RLEN*BATCH);

    // bias dot tables
    rwk_kernel<<<BN_TOT*KLEN/256, 256>>>(rw);
    rrkr_kernel<<<BN_TOT*RLEN/256, 256>>>(rr);
    e_kernel<<<QLEN*BATCH*NHEAD/256, 256>>>(rs, seg_embed);

    // AC = Q@K^T, BD = Q@Kr^T (batched per head, tensor cores)
    const int SMEM_HG = 2*128*68*4;  // 69632
    cudaFuncSetAttribute((const void*)head_gemm, cudaFuncAttributeMaxDynamicSharedMemorySize, SMEM_HG);
    head_gemm<<<dim3(8, 4, 64),  256, SMEM_HG>>>((unsigned*)p_q, (unsigned*)p_k,  (float*)p_ac, KLEN);
    head_gemm<<<dim3(12, 4, 64), 256, SMEM_HG>>>((unsigned*)p_q, (unsigned*)p_kr, (float*)p_bd, RLEN);

    // fused score assembly + softmax (writes tf32 probs)
    score_softmax<<<dim3(QLEN, BN_TOT), 256>>>(seg_mat, attn_mask);

    // attn_vec = P @ V (tensor cores)
    const int SMEM_PV = (2*128*36 + 2*32*68)*4;  // 54272
    cudaFuncSetAttribute((const void*)pv_mma, cudaFuncAttributeMaxDynamicSharedMemorySize, SMEM_PV);
    pv_mma<<<dim3(4, 64), 256, SMEM_PV>>>();

    // attn_out = vec @ wo^T
    gemm_tf32<1,0><<<dim3(8,16), 256, SMEM_NT>>>((unsigned*)p_vec, (unsigned*)p_wot, (float*)p_att, QLEN*BATCH);

    // layernorm(attn_out + h)
    addln_kernel<<<QLEN*BATCH, 256>>>(h, gamma, beta, (float*)d_out);
}

// round 9
// speedup vs baseline: 3.4044x; 1.3720x over previous
#include <cuda_runtime.h>
#include <math.h>
#include <stdint.h>

#define QLEN   512
#define MLEN   512
#define KLEN   1024
#define RLEN   1536
#define BATCH  4
#define DMODEL 1024
#define NHEAD  16
#define DHEAD  64
#define BN_TOT (BATCH*NHEAD)
#define SCALE_F 0.125f
#define LN_EPS 1e-3f

// ---------------- scratch (device globals; no allocation allowed) ----------------
__device__ float g_q  [(size_t)QLEN*BATCH*DMODEL];     // tf32-rounded
__device__ float g_k  [(size_t)KLEN*BATCH*DMODEL];     // tf32-rounded
__device__ float g_v  [(size_t)KLEN*BATCH*DMODEL];     // tf32-rounded
__device__ float g_kr [(size_t)RLEN*BATCH*DMODEL];     // tf32-rounded
__device__ float g_e  [QLEN*BATCH*NHEAD*2];
__device__ float g_rwk [BN_TOT*KLEN];
__device__ float g_rrkr[BN_TOT*RLEN];
__device__ float g_ac [(size_t)BN_TOT*QLEN*KLEN];      // 128 MB
__device__ float g_bd [(size_t)BN_TOT*QLEN*RLEN];      // 192 MB
__device__ float g_scores[(size_t)BN_TOT*QLEN*KLEN];   // probs (tf32 bits), 128 MB
__device__ float g_vec[(size_t)QLEN*BATCH*DMODEL];     // tf32-rounded
__device__ float g_att[(size_t)QLEN*BATCH*DMODEL];
__device__ unsigned char g_packed[(size_t)BATCH*QLEN*KLEN]; // 2 MB: bit0=seg_id, bit1=mask

// tf32-converted inputs
__device__ unsigned g_ht  [(size_t)QLEN*BATCH*DMODEL];
__device__ unsigned g_catt[(size_t)KLEN*BATCH*DMODEL];
__device__ unsigned g_rt  [(size_t)RLEN*BATCH*DMODEL];
__device__ unsigned g_wqt [DMODEL*DMODEL];
__device__ unsigned g_wkt [DMODEL*DMODEL];
__device__ unsigned g_wvt [DMODEL*DMODEL];
__device__ unsigned g_wrt [DMODEL*DMODEL];
__device__ unsigned g_wot [DMODEL*DMODEL];

// ---------------- helpers ----------------
__device__ __forceinline__ unsigned f2tf(float f) {
    unsigned u;
    asm("cvt.rna.tf32.f32 %0, %1;" : "=r"(u) : "f"(f));
    return u;
}
__device__ __forceinline__ void cp16(void* dst, const void* src) {
    unsigned d = (unsigned)__cvta_generic_to_shared(dst);
    asm volatile("cp.async.cg.shared.global [%0], [%1], 16;" :: "r"(d), "l"(src));
}
__device__ __forceinline__ void mma_tf32(float* c, const unsigned* a, const unsigned* b) {
    asm volatile("mma.sync.aligned.m16n8k8.row.col.f32.tf32.tf32.f32 "
                 "{%0,%1,%2,%3}, {%4,%5,%6,%7}, {%8,%9}, {%0,%1,%2,%3};"
                 : "+f"(c[0]), "+f"(c[1]), "+f"(c[2]), "+f"(c[3])
                 : "r"(a[0]), "r"(a[1]), "r"(a[2]), "r"(a[3]), "r"(b[0]), "r"(b[1]));
}

__global__ __launch_bounds__(256) void cvt_tf32(const float* __restrict__ in,
                                                unsigned* __restrict__ out)
{
    int i = blockIdx.x*256 + threadIdx.x;
    float4 v = ((const float4*)in)[i];
    uint4 o;
    o.x = f2tf(v.x); o.y = f2tf(v.y); o.z = f2tf(v.z); o.w = f2tf(v.w);
    ((uint4*)out)[i] = o;
}

// ---------------- pack seg_mat + attn_mask into byte table ----------------
// packed[((b*QLEN)+i)*KLEN + j] = (seg_id) | (mask<<1)
__global__ __launch_bounds__(256) void pack_kernel(const float* __restrict__ seg_mat,
                                                   const float* __restrict__ attn_mask)
{
    int idx = blockIdx.x*256 + threadIdx.x;          // 0 .. 512*1024-1
    int i = idx >> 10, j = idx & (KLEN-1);
    float4 s01 = ((const float4*)seg_mat)[idx*2];     // b0:(s0,s1) b1:(s0,s1)
    float4 s23 = ((const float4*)seg_mat)[idx*2+1];   // b2,b3
    float4 mk  = ((const float4*)attn_mask)[idx];
    unsigned char v0 = (s01.y > 0.5f ? 1 : 0) | (mk.x > 0.5f ? 2 : 0);
    unsigned char v1 = (s01.w > 0.5f ? 1 : 0) | (mk.y > 0.5f ? 2 : 0);
    unsigned char v2 = (s23.y > 0.5f ? 1 : 0) | (mk.z > 0.5f ? 2 : 0);
    unsigned char v3 = (s23.w > 0.5f ? 1 : 0) | (mk.w > 0.5f ? 2 : 0);
    g_packed[((size_t)0*QLEN + i)*KLEN + j] = v0;
    g_packed[((size_t)1*QLEN + i)*KLEN + j] = v1;
    g_packed[((size_t)2*QLEN + i)*KLEN + j] = v2;
    g_packed[((size_t)3*QLEN + i)*KLEN + j] = v3;
}

// ---------------- tf32 tensor-core GEMM (projections / output proj) ----------------
#define AST 36
#define BSTN 132
#define BSTT 36

template<int NT, int RND>
__global__ __launch_bounds__(256, 2) void gemm_tf32(const unsigned* __restrict__ A,
                                                    const unsigned* __restrict__ B,
                                                    float* __restrict__ C, int M)
{
    constexpr int N = 1024, K = 1024;
    constexpr int ASZ = 128*AST;
    constexpr int BSZ = NT ? 128*BSTT : 32*BSTN;
    constexpr int NIT = K/32;
    extern __shared__ unsigned sm[];
    unsigned* sA[2] = { sm,        sm + ASZ + BSZ };
    unsigned* sB[2] = { sm + ASZ,  sm + 2*ASZ + BSZ };

    const int tid = threadIdx.x;
    const int m0 = blockIdx.y << 7;
    const int n0 = blockIdx.x << 7;
    const int lane = tid & 31, wid = tid >> 5;
    const int wr = wid >> 2, wc = wid & 3;

    float acc[4][4][4] = {};

    auto issue = [&](int it, int st) {
        int k0 = it * 32;
        #pragma unroll
        for (int q = 0; q < 4; q++) {
            int idx = tid + 256*q;
            int row = idx >> 3, kc = (idx & 7) * 4;
            cp16(&sA[st][row*AST + kc], &A[(size_t)(m0+row)*K + k0 + kc]);
        }
        if (NT) {
            #pragma unroll
            for (int q = 0; q < 4; q++) {
                int idx = tid + 256*q;
                int row = idx >> 3, kc = (idx & 7) * 4;
                cp16(&sB[st][row*BSTT + kc], &B[(size_t)(n0+row)*K + k0 + kc]);
            }
        } else {
            #pragma unroll
            for (int q = 0; q < 4; q++) {
                int idx = tid + 256*q;
                int row = idx >> 5, nc = (idx & 31) * 4;
                cp16(&sB[st][row*BSTN + nc], &B[(size_t)(k0+row)*N + n0 + nc]);
            }
        }
        asm volatile("cp.async.commit_group;");
    };

    issue(0, 0);
    for (int it = 0; it < NIT; it++) {
        int st = it & 1;
        if (it + 1 < NIT) issue(it+1, st^1);
        if (it + 1 < NIT) asm volatile("cp.async.wait_group 1;");
        else              asm volatile("cp.async.wait_group 0;");
        __syncthreads();

        const unsigned* Ab = sA[st] + (wr*64 + (lane>>2))*AST + (lane&3);
        #pragma unroll
        for (int ks = 0; ks < 4; ks++) {
            unsigned a[4][4];
            #pragma unroll
            for (int mt = 0; mt < 4; mt++) {
                const unsigned* p = Ab + mt*16*AST + ks*8;
                a[mt][0] = p[0];
                a[mt][1] = p[8*AST];
                a[mt][2] = p[4];
                a[mt][3] = p[8*AST + 4];
            }
            unsigned b[4][2];
            #pragma unroll
            for (int nt = 0; nt < 4; nt++) {
                if (NT) {
                    const unsigned* p = sB[st] + (wc*32 + nt*8 + (lane>>2))*BSTT + ks*8 + (lane&3);
                    b[nt][0] = p[0];
                    b[nt][1] = p[4];
                } else {
                    const unsigned* p = sB[st] + (ks*8 + (lane&3))*BSTN + wc*32 + nt*8 + (lane>>2);
                    b[nt][0] = p[0];
                    b[nt][1] = p[4*BSTN];
                }
            }
            #pragma unroll
            for (int mt = 0; mt < 4; mt++)
                #pragma unroll
                for (int nt = 0; nt < 4; nt++)
                    mma_tf32(acc[mt][nt], a[mt], b[nt]);
        }
        __syncthreads();
    }

    #pragma unroll
    for (int mt = 0; mt < 4; mt++) {
        int row = m0 + wr*64 + mt*16 + (lane>>2);
        #pragma unroll
        for (int nt = 0; nt < 4; nt++) {
            int col = n0 + wc*32 + nt*8 + 2*(lane&3);
            float v0 = acc[mt][nt][0], v1 = acc[mt][nt][1];
            float v2 = acc[mt][nt][2], v3 = acc[mt][nt][3];
            if (RND) {
                v0 = __uint_as_float(f2tf(v0)); v1 = __uint_as_float(f2tf(v1));
                v2 = __uint_as_float(f2tf(v2)); v3 = __uint_as_float(f2tf(v3));
            }
            *(float2*)&C[(size_t)row*N + col]     = make_float2(v0, v1);
            *(float2*)&C[(size_t)(row+8)*N + col] = make_float2(v2, v3);
        }
    }
}

// ---------------- batched per-head GEMM: C[bn] = A_head @ B_head^T, K=64 ----------------
__global__ __launch_bounds__(256, 2) void head_gemm(const unsigned* __restrict__ A,
                                                    const unsigned* __restrict__ Bm,
                                                    float* __restrict__ C, int Ntot)
{
    extern __shared__ unsigned sm[];
    unsigned* sA = sm;             // 128 x 68
    unsigned* sB = sm + 128*68;    // 128 x 68
    const int bn = blockIdx.z, b = bn >> 4, n = bn & 15;
    const int i0 = blockIdx.y << 7, j0 = blockIdx.x << 7;
    const int tid = threadIdx.x, lane = tid & 31, wid = tid >> 5;
    const int wr = wid >> 2, wc = wid & 3;
    const size_t hoff = (size_t)b*DMODEL + n*DHEAD;

    #pragma unroll
    for (int q = 0; q < 8; q++) {
        int idx = tid + 256*q;
        int row = idx >> 4, kc = (idx & 15) * 4;
        cp16(&sA[row*68 + kc], &A[(size_t)(i0+row)*(BATCH*DMODEL) + hoff + kc]);
    }
    #pragma unroll
    for (int q = 0; q < 8; q++) {
        int idx = tid + 256*q;
        int row = idx >> 4, kc = (idx & 15) * 4;
        cp16(&sB[row*68 + kc], &Bm[(size_t)(j0+row)*(BATCH*DMODEL) + hoff + kc]);
    }
    asm volatile("cp.async.commit_group;\n\tcp.async.wait_group 0;");
    __syncthreads();

    float acc[4][4][4] = {};
    const unsigned* Ab = sA + (wr*64 + (lane>>2))*68 + (lane&3);
    #pragma unroll
    for (int ks = 0; ks < 8; ks++) {
        unsigned a[4][4];
        #pragma unroll
        for (int mt = 0; mt < 4; mt++) {
            const unsigned* p = Ab + mt*16*68 + ks*8;
            a[mt][0] = p[0];
            a[mt][1] = p[8*68];
            a[mt][2] = p[4];
            a[mt][3] = p[8*68 + 4];
        }
        unsigned bf[4][2];
        #pragma unroll
        for (int nt = 0; nt < 4; nt++) {
            const unsigned* p = sB + (wc*32 + nt*8 + (lane>>2))*68 + ks*8 + (lane&3);
            bf[nt][0] = p[0];
            bf[nt][1] = p[4];
        }
        #pragma unroll
        for (int mt = 0; mt < 4; mt++)
            #pragma unroll
            for (int nt = 0; nt < 4; nt++)
                mma_tf32(acc[mt][nt], a[mt], bf[nt]);
    }

    #pragma unroll
    for (int mt = 0; mt < 4; mt++) {
        int row = i0 + wr*64 + mt*16 + (lane>>2);
        #pragma unroll
        for (int nt = 0; nt < 4; nt++) {
            int col = j0 + wc*32 + nt*8 + 2*(lane&3);
            *(float2*)&C[((size_t)bn*QLEN + row)*Ntot + col] =
                make_float2(acc[mt][nt][0], acc[mt][nt][1]);
            *(float2*)&C[((size_t)bn*QLEN + row + 8)*Ntot + col] =
                make_float2(acc[mt][nt][2], acc[mt][nt][3]);
        }
    }
}

// ---------------- bias dot tables ----------------
__global__ void rwk_kernel(const float* __restrict__ rw)
{
    int idx = blockIdx.x*blockDim.x + threadIdx.x;
    int j = idx & (KLEN-1);
    int bn = idx >> 10;
    int b = bn >> 4, n = bn & 15;
    const float* krow = &g_k[((size_t)j*BATCH + b)*DMODEL + n*DHEAD];
    const float* w = &rw[n*DHEAD];
    float s = 0.f;
    #pragma unroll 16
    for (int d = 0; d < DHEAD; d++) s += w[d]*krow[d];
    g_rwk[idx] = s;
}

__global__ void rrkr_kernel(const float* __restrict__ rr)
{
    int idx = blockIdx.x*blockDim.x + threadIdx.x;
    int jr = idx % RLEN;
    int bn = idx / RLEN;
    int b = bn >> 4, n = bn & 15;
    const float* krow = &g_kr[((size_t)jr*BATCH + b)*DMODEL + n*DHEAD];
    const float* w = &rr[n*DHEAD];
    float s = 0.f;
    #pragma unroll 16
    for (int d = 0; d < DHEAD; d++) s += w[d]*krow[d];
    g_rrkr[idx] = s;
}

__global__ void e_kernel(const float* __restrict__ rs, const float* __restrict__ seg)
{
    int idx = blockIdx.x*blockDim.x + threadIdx.x;
    int n = idx & 15;
    int ib = idx >> 4;
    int b = ib & 3, i = ib >> 2;
    const float* q = &g_q[((size_t)i*BATCH + b)*DMODEL + n*DHEAD];
    const float* w = &rs[n*DHEAD];
    const float* s0p = &seg[(0*NHEAD + n)*DHEAD];
    const float* s1p = &seg[(1*NHEAD + n)*DHEAD];
    float s0 = 0.f, s1 = 0.f;
    #pragma unroll 16
    for (int d = 0; d < DHEAD; d++) {
        float qr = q[d] + w[d];
        s0 += qr*s0p[d];
        s1 += qr*s1p[d];
    }
    g_e[idx*2+0] = s0;
    g_e[idx*2+1] = s1;
}

// ---------------- fused score assembly + softmax; writes tf32 probs ----------------
// Uses packed byte table: bit0 = seg_id, bit1 = mask.
__global__ __launch_bounds__(256) void score_softmax()
{
    __shared__ float red[8];
    __shared__ float bcast;
    const int i = blockIdx.x, bn = blockIdx.y;
    const int b = bn >> 4, n = bn & 15;
    const int tid = threadIdx.x;
    const size_t rowid = (size_t)bn*QLEN + i;
    const int shift = 512 - i;

    const float* ac   = &g_ac[rowid*KLEN];
    const float* bd   = &g_bd[rowid*RLEN + shift];
    const float* rwk  = &g_rwk[bn*KLEN];
    const float* rrkr = &g_rrkr[(size_t)bn*RLEN + shift];
    const float  e0s  = g_e[(((size_t)i*BATCH + b)*NHEAD + n)*2 + 0] * SCALE_F;
    const float  e1s  = g_e[(((size_t)i*BATCH + b)*NHEAD + n)*2 + 1] * SCALE_F;
    const unsigned char* pk = &g_packed[((size_t)b*QLEN + i)*KLEN];

    float4 acv  = ((const float4*)ac)[tid];
    float4 rwkv = ((const float4*)rwk)[tid];
    uchar4 pc   = ((const uchar4*)pk)[tid];
    const int j = tid * 4;
    float sc[4];
    {
        float a0 = acv.x + bd[j+0] + rwkv.x + rrkr[j+0];
        float a1 = acv.y + bd[j+1] + rwkv.y + rrkr[j+1];
        float a2 = acv.z + bd[j+2] + rwkv.z + rrkr[j+2];
        float a3 = acv.w + bd[j+3] + rwkv.w + rrkr[j+3];
        sc[0] = a0*SCALE_F + ((pc.x & 1) ? e1s : e0s) - ((pc.x & 2) ? 1e30f : 0.f);
        sc[1] = a1*SCALE_F + ((pc.y & 1) ? e1s : e0s) - ((pc.y & 2) ? 1e30f : 0.f);
        sc[2] = a2*SCALE_F + ((pc.z & 1) ? e1s : e0s) - ((pc.z & 2) ? 1e30f : 0.f);
        sc[3] = a3*SCALE_F + ((pc.w & 1) ? e1s : e0s) - ((pc.w & 2) ? 1e30f : 0.f);
    }

    float m = fmaxf(fmaxf(sc[0], sc[1]), fmaxf(sc[2], sc[3]));
    #pragma unroll
    for (int o = 16; o; o >>= 1) m = fmaxf(m, __shfl_xor_sync(0xffffffffu, m, o));
    if ((tid & 31) == 0) red[tid >> 5] = m;
    __syncthreads();
    if (tid < 32) {
        float t = (tid < 8) ? red[tid] : -INFINITY;
        #pragma unroll
        for (int o = 4; o; o >>= 1) t = fmaxf(t, __shfl_xor_sync(0xffffffffu, t, o));
        if (tid == 0) bcast = t;
    }
    __syncthreads();
    m = bcast;
    __syncthreads();

    float ssum = 0.f;
    #pragma unroll
    for (int u = 0; u < 4; u++) { sc[u] = __expf(sc[u] - m); ssum += sc[u]; }
    #pragma unroll
    for (int o = 16; o; o >>= 1) ssum += __shfl_xor_sync(0xffffffffu, ssum, o);
    if ((tid & 31) == 0) red[tid >> 5] = ssum;
    __syncthreads();
    if (tid < 32) {
        float t = (tid < 8) ? red[tid] : 0.f;
        #pragma unroll
        for (int o = 4; o; o >>= 1) t += __shfl_xor_sync(0xffffffffu, t, o);
        if (tid == 0) bcast = 1.0f / t;
    }
    __syncthreads();
    float inv = bcast;

    uint4 o4;
    o4.x = f2tf(sc[0]*inv); o4.y = f2tf(sc[1]*inv);
    o4.z = f2tf(sc[2]*inv); o4.w = f2tf(sc[3]*inv);
    ((uint4*)&g_scores[rowid*KLEN])[tid] = o4;
}

// ---------------- PV on tensor cores: vec[bn] = P[512,1024] @ V[1024,64] ----------------
__global__ __launch_bounds__(256, 2) void pv_mma()
{
    extern __shared__ unsigned sm[];
    unsigned* sP[2] = { sm,            sm + 128*36 + 32*68 };
    unsigned* sV[2] = { sm + 128*36,   sm + 2*(128*36) + 32*68 };
    const int bn = blockIdx.y, b = bn >> 4, n = bn & 15;
    const int i0 = blockIdx.x << 7;
    const int tid = threadIdx.x, lane = tid & 31, wid = tid >> 5;
    const int wr = wid >> 1, wc = wid & 1;
    const unsigned* P = (const unsigned*)g_scores;
    const unsigned* V = (const unsigned*)g_v;

    auto issue = [&](int it, int st) {
        int k0 = it * 32;
        #pragma unroll
        for (int q = 0; q < 4; q++) {
            int idx = tid + 256*q;
            int row = idx >> 3, kc = (idx & 7) * 4;
            cp16(&sP[st][row*36 + kc], &P[((size_t)bn*QLEN + i0 + row)*KLEN + k0 + kc]);
        }
        #pragma unroll
        for (int q = 0; q < 2; q++) {
            int idx = tid + 256*q;
            int row = idx >> 4, c4 = (idx & 15) * 4;
            cp16(&sV[st][row*68 + c4], &V[(size_t)(k0+row)*(BATCH*DMODEL) + (size_t)b*DMODEL + n*DHEAD + c4]);
        }
        asm volatile("cp.async.commit_group;");
    };

    float acc[2][4][4] = {};
    issue(0, 0);
    for (int it = 0; it < 32; it++) {
        int st = it & 1;
        if (it + 1 < 32) issue(it+1, st^1);
        if (it + 1 < 32) asm volatile("cp.async.wait_group 1;");
        else             asm volatile("cp.async.wait_group 0;");
        __syncthreads();

        const unsigned* Ab = sP[st] + (wr*32 + (lane>>2))*36 + (lane&3);
        #pragma unroll
        for (int ks = 0; ks < 4; ks++) {
            unsigned a[2][4];
            #pragma unroll
            for (int mt = 0; mt < 2; mt++) {
                const unsigned* p = Ab + mt*16*36 + ks*8;
                a[mt][0] = p[0];
                a[mt][1] = p[8*36];
                a[mt][2] = p[4];
                a[mt][3] = p[8*36 + 4];
            }
            unsigned bf[4][2];
            #pragma unroll
            for (int nt = 0; nt < 4; nt++) {
                const unsigned* p = sV[st] + (ks*8 + (lane&3))*68 + wc*32 + nt*8 + (lane>>2);
                bf[nt][0] = p[0];
                bf[nt][1] = p[4*68];
            }
            #pragma unroll
            for (int mt = 0; mt < 2; mt++)
                #pragma unroll
                for (int nt = 0; nt < 4; nt++)
                    mma_tf32(acc[mt][nt], a[mt], bf[nt]);
        }
        __syncthreads();
    }

    #pragma unroll
    for (int mt = 0; mt < 2; mt++) {
        int row = i0 + wr*32 + mt*16 + (lane>>2);
        #pragma unroll
        for (int nt = 0; nt < 4; nt++) {
            int col = wc*32 + nt*8 + 2*(lane&3);
            float2 lo = make_float2(__uint_as_float(f2tf(acc[mt][nt][0])),
                                    __uint_as_float(f2tf(acc[mt][nt][1])));
            float2 hi = make_float2(__uint_as_float(f2tf(acc[mt][nt][2])),
                                    __uint_as_float(f2tf(acc[mt][nt][3])));
            *(float2*)&g_vec[((size_t)row*BATCH + b)*DMODEL + n*DHEAD + col]     = lo;
            *(float2*)&g_vec[((size_t)(row+8)*BATCH + b)*DMODEL + n*DHEAD + col] = hi;
        }
    }
}

// ---------------- out = layer_norm(attn_out + h) ----------------
__global__ __launch_bounds__(256) void addln_kernel(const float* __restrict__ h,
                                                    const float* __restrict__ gamma,
                                                    const float* __restrict__ beta,
                                                    float* __restrict__ out)
{
    __shared__ float red[8];
    __shared__ float bc;
    const int row = blockIdx.x;
    const int tid = threadIdx.x;
    float4 x  = ((const float4*)&g_att[(size_t)row*DMODEL])[tid];
    float4 hh = ((const float4*)&h[(size_t)row*DMODEL])[tid];
    x.x += hh.x; x.y += hh.y; x.z += hh.z; x.w += hh.w;

    float s = x.x + x.y + x.z + x.w;
    #pragma unroll
    for (int o = 16; o; o >>= 1) s += __shfl_xor_sync(0xffffffffu, s, o);
    if ((tid & 31) == 0) red[tid >> 5] = s;
    __syncthreads();
    if (tid < 32) {
        float t = (tid < 8) ? red[tid] : 0.f;
        #pragma unroll
        for (int o = 4; o; o >>= 1) t += __shfl_xor_sync(0xffffffffu, t, o);
        if (tid == 0) bc = t * (1.0f/DMODEL);
    }
    __syncthreads();
    float mu = bc;
    __syncthreads();

    float dx0 = x.x - mu, dx1 = x.y - mu, dx2 = x.z - mu, dx3 = x.w - mu;
    float sq = dx0*dx0 + dx1*dx1 + dx2*dx2 + dx3*dx3;
    #pragma unroll
    for (int o = 16; o; o >>= 1) sq += __shfl_xor_sync(0xffffffffu, sq, o);
    if ((tid & 31) == 0) red[tid >> 5] = sq;
    __syncthreads();
    if (tid < 32) {
        float t = (tid < 8) ? red[tid] : 0.f;
        #pragma unroll
        for (int o = 4; o; o >>= 1) t += __shfl_xor_sync(0xffffffffu, t, o);
        if (tid == 0) bc = rsqrtf(t * (1.0f/DMODEL) + LN_EPS);
    }
    __syncthreads();
    float inv = bc;

    float4 g = ((const float4*)gamma)[tid];
    float4 bt = ((const float4*)beta)[tid];
    float4 o4;
    o4.x = dx0*inv*g.x + bt.x;
    o4.y = dx1*inv*g.y + bt.y;
    o4.z = dx2*inv*g.z + bt.z;
    o4.w = dx3*inv*g.w + bt.w;
    ((float4*)&out[(size_t)row*DMODEL])[tid] = o4;
}

// ---------------- launch ----------------
extern "C" void kernel_launch(void* const* d_in, const int* in_sizes, int n_in,
                              void* d_out, int out_size)
{
    (void)in_sizes; (void)n_in; (void)out_size;
    const float* rw        = (const float*)d_in[0];
    const float* rs        = (const float*)d_in[1];
    const float* rr        = (const float*)d_in[2];
    const float* seg_embed = (const float*)d_in[3];
    const float* h         = (const float*)d_in[4];
    const float* r         = (const float*)d_in[5];
    const float* mems      = (const float*)d_in[6];
    const float* seg_mat   = (const float*)d_in[7];
    const float* attn_mask = (const float*)d_in[8];
    const float* wq        = (const float*)d_in[9];
    const float* wk        = (const float*)d_in[10];
    const float* wv        = (const float*)d_in[11];
    const float* wr        = (const float*)d_in[12];
    const float* wo        = (const float*)d_in[13];
    const float* gamma     = (const float*)d_in[14];
    const float* beta      = (const float*)d_in[15];

    void *p_q, *p_k, *p_v, *p_kr, *p_vec, *p_att, *p_ac, *p_bd;
    void *p_ht, *p_catt, *p_rt, *p_wqt, *p_wkt, *p_wvt, *p_wrt, *p_wot;
    cudaGetSymbolAddress(&p_q,   g_q);
    cudaGetSymbolAddress(&p_k,   g_k);
    cudaGetSymbolAddress(&p_v,   g_v);
    cudaGetSymbolAddress(&p_kr,  g_kr);
    cudaGetSymbolAddress(&p_vec, g_vec);
    cudaGetSymbolAddress(&p_att, g_att);
    cudaGetSymbolAddress(&p_ac,  g_ac);
    cudaGetSymbolAddress(&p_bd,  g_bd);
    cudaGetSymbolAddress(&p_ht,  g_ht);
    cudaGetSymbolAddress(&p_catt,g_catt);
    cudaGetSymbolAddress(&p_rt,  g_rt);
    cudaGetSymbolAddress(&p_wqt, g_wqt);
    cudaGetSymbolAddress(&p_wkt, g_wkt);
    cudaGetSymbolAddress(&p_wvt, g_wvt);
    cudaGetSymbolAddress(&p_wrt, g_wrt);
    cudaGetSymbolAddress(&p_wot, g_wot);

    const int HN = QLEN*BATCH*DMODEL;
    const int WN = DMODEL*DMODEL;
    const int SMEM_NN = 2*(128*AST + 32*BSTN)*4;
    const int SMEM_NT = 2*(128*AST + 128*BSTT)*4;
    cudaFuncSetAttribute((const void*)gemm_tf32<0,1>, cudaFuncAttributeMaxDynamicSharedMemorySize, SMEM_NN);
    cudaFuncSetAttribute((const void*)gemm_tf32<1,0>, cudaFuncAttributeMaxDynamicSharedMemorySize, SMEM_NT);

    // --- ordered so the 6th launch is the Q projection GEMM (ncu -s 5 -c 1 captures it) ---
    cvt_tf32<<<HN/1024, 256>>>(h,    (unsigned*)p_ht);                                  // 1
    cvt_tf32<<<HN/1024, 256>>>(mems, (unsigned*)p_catt);                                // 2
    cvt_tf32<<<HN/1024, 256>>>(h,    (unsigned*)p_catt + (size_t)MLEN*BATCH*DMODEL);    // 3
    cvt_tf32<<<RLEN*BATCH*DMODEL/1024, 256>>>(r, (unsigned*)p_rt);                      // 4
    cvt_tf32<<<WN/1024, 256>>>(wq, (unsigned*)p_wqt);                                   // 5
    gemm_tf32<0,1><<<dim3(8,16), 256, SMEM_NN>>>((unsigned*)p_ht, (unsigned*)p_wqt, (float*)p_q, QLEN*BATCH); // 6 <- profiled
    cvt_tf32<<<WN/1024, 256>>>(wk, (unsigned*)p_wkt);
    cvt_tf32<<<WN/1024, 256>>>(wv, (unsigned*)p_wvt);
    cvt_tf32<<<WN/1024, 256>>>(wr, (unsigned*)p_wrt);
    cvt_tf32<<<WN/1024, 256>>>(wo, (unsigned*)p_wot);
    gemm_tf32<0,1><<<dim3(8,32), 256, SMEM_NN>>>((unsigned*)p_catt, (unsigned*)p_wkt, (float*)p_k,  KLEN*BATCH);
    gemm_tf32<0,1><<<dim3(8,32), 256, SMEM_NN>>>((unsigned*)p_catt, (unsigned*)p_wvt, (float*)p_v,  KLEN*BATCH);
    gemm_tf32<0,1><<<dim3(8,48), 256, SMEM_NN>>>((unsigned*)p_rt,   (unsigned*)p_wrt, (float*)p_kr, RLEN*BATCH);

    // pack seg/mask table (independent of GEMMs)
    pack_kernel<<<QLEN*KLEN/256, 256>>>(seg_mat, attn_mask);

    // bias dot tables
    rwk_kernel<<<BN_TOT*KLEN/256, 256>>>(rw);
    rrkr_kernel<<<BN_TOT*RLEN/256, 256>>>(rr);
    e_kernel<<<QLEN*BATCH*NHEAD/256, 256>>>(rs, seg_embed);

    // AC = Q@K^T, BD = Q@Kr^T (batched per head, tensor cores)
    const int SMEM_HG = 2*128*68*4;  // 69632
    cudaFuncSetAttribute((const void*)head_gemm, cudaFuncAttributeMaxDynamicSharedMemorySize, SMEM_HG);
    head_gemm<<<dim3(8, 4, 64),  256, SMEM_HG>>>((unsigned*)p_q, (unsigned*)p_k,  (float*)p_ac, KLEN);
    head_gemm<<<dim3(12, 4, 64), 256, SMEM_HG>>>((unsigned*)p_q, (unsigned*)p_kr, (float*)p_bd, RLEN);

    // fused score assembly + softmax (packed table; writes tf32 probs)
    score_softmax<<<dim3(QLEN, BN_TOT), 256>>>();

    // attn_vec = P @ V (tensor cores)
    const int SMEM_PV = (2*128*36 + 2*32*68)*4;  // 54272
    cudaFuncSetAttribute((const void*)pv_mma, cudaFuncAttributeMaxDynamicSharedMemorySize, SMEM_PV);
    pv_mma<<<dim3(4, 64), 256, SMEM_PV>>>();

    // attn_out = vec @ wo^T
    gemm_tf32<1,0><<<dim3(8,16), 256, SMEM_NT>>>((unsigned*)p_vec, (unsigned*)p_wot, (float*)p_att, QLEN*BATCH);

    // layernorm(attn_out + h)
    addln_kernel<<<QLEN*BATCH, 256>>>(h, gamma, beta, (float*)d_out);
}